// round 13
// baseline (speedup 1.0000x reference)
#include <cuda_runtime.h>
#include <cuda_fp16.h>

#define NN 65536
#define EE 524288
#define BB 1024
#define FEATN 64
#define NCLS 5
#define INF_F __int_as_float(0x7f800000)

#define TAB_BYTES (8 * 65 * 68 * 4)          // 141440
#define G2_SMEM   (TAB_BYTES + 512 * 4)      // + thr table

// ---------------- scratch (device globals; no allocs allowed) ----------------
__device__ float d_p[4], d_q[4], d_r[4], d_t[4];
__device__ __align__(16) float4 d_S0[NN];          // zero at entry (self-cleaning)
__device__ __align__(16) float4 d_S1[NN];
__device__ __align__(16) __half2 d_gh[NN * 32];
__device__ float d_a2s[NN];
__device__ float d_a2d[NN];
__device__ float d_den2[NN];
__device__ __align__(16) __half2 d_out2h[NN * 32];
__device__ __align__(16) float d_pool[BB * 64];    // zero at entry (self-cleaning)
__device__ float d_fa[64];                          // zero at entry (self-cleaning)
__device__ int d_ctr;                               // zero at entry (self-cleaning)
__device__ float d_thr[8 * 64];
__device__ __align__(16) __half2 d_tab[8 * 65 * 68];
__device__ __align__(16) __half2 d_faW1h[64 * 32];
__device__ __align__(8)  __half2 d_fab1h[32];
__device__ __align__(8)  __half2 d_faW2h[32];

__device__ __forceinline__ unsigned pack_h2(float a, float b) {
    __half2 h = __floats2half2_rn(a, b);
    return *(unsigned*)&h;
}

// ---------------- prep: tables (blocks 0-7) + p/q/r/t + fa packing (block 8) ----------------
__global__ void prep_k(const float* __restrict__ Win, const float* __restrict__ bin,
                       const float* __restrict__ W1, const float* __restrict__ a1s,
                       const float* __restrict__ a1d, const float* __restrict__ b1,
                       const float* __restrict__ W2, const float* __restrict__ a2sv,
                       const float* __restrict__ a2dv, const float* __restrict__ faW1,
                       const float* __restrict__ fab1, const float* __restrict__ faW2) {
    int b = blockIdx.x;
    int tid = threadIdx.x;      // 256
    if (b < 8) {
        int hs = b, h = hs >> 1, set = hs & 1;
        __shared__ float W2s[64 * 68];
        __shared__ float us[64], vbs[64], key[64];
        __shared__ int sidx[64];
        __shared__ unsigned char memb[64];
        __shared__ int n_s;
        if (tid < 64) {
            float u = 0.f, v = 0.f;
            for (int k = 0; k < 64; k++) {
                float w1 = W1[k * 256 + h * 64 + tid];
                u += Win[k] * w1;
                v += bin[k] * w1;
            }
            float vb = v + b1[h * 64 + tid];
            us[tid] = u; vbs[tid] = vb;
            bool m = (set == 0) ? (u > 0.f) : (u < 0.f);
            memb[tid] = m ? 1 : 0;
            key[tid] = m ? (-vb / u) : INF_F;
        }
        for (int i = tid; i < 64 * 64; i += 256) {
            int j = i >> 6, c = i & 63;
            W2s[j * 68 + c] = W2[(h * 64 + j) * 64 + c];
        }
        __syncthreads();
        if (tid < 64) {
            float as = 0.f, ad = 0.f;
            for (int c = 0; c < 64; c++) {
                float w2 = W2s[tid * 68 + c];
                as += w2 * a2sv[c];
                ad += w2 * a2dv[c];
            }
            W2s[tid * 68 + 64] = as;
            W2s[tid * 68 + 65] = ad;
            W2s[tid * 68 + 66] = 0.f;
            W2s[tid * 68 + 67] = 0.f;
        }
        __syncthreads();
        if (tid < 64) {
            float ki = key[tid];
            int r = 0;
            for (int j = 0; j < 64; j++) {
                float kj = key[j];
                r += (kj < ki) || (kj == ki && j < tid);
            }
            sidx[r] = tid;
        }
        if (tid == 0) {
            int n = 0;
            for (int j = 0; j < 64; j++) n += memb[j];
            n_s = n;
        }
        __syncthreads();
        int n = n_s;
        if (tid < 64) d_thr[hs * 64 + tid] = key[sidx[tid]];
        if (tid < 68) {
            int c = tid;
            if (set == 0) {
                float base = 0.f;
                for (int j = 0; j < 64; j++)
                    if (us[j] == 0.f && vbs[j] > 0.f) base += vbs[j] * W2s[j * 68 + c];
                float au = 0.f, av = base;
                d_tab[(hs * 65 + 0) * 68 + c] = __float22half2_rn(make_float2(au, av));
                for (int s = 0; s < 64; s++) {
                    if (s < n) {
                        int k = sidx[s];
                        au += us[k] * W2s[k * 68 + c];
                        av += vbs[k] * W2s[k * 68 + c];
                    }
                    d_tab[(hs * 65 + s + 1) * 68 + c] = __float22half2_rn(make_float2(au, av));
                }
            } else {
                for (int s = n; s <= 64; s++)
                    d_tab[(hs * 65 + s) * 68 + c] = __float22half2_rn(make_float2(0.f, 0.f));
                float au = 0.f, av = 0.f;
                for (int s = n - 1; s >= 0; s--) {
                    int k = sidx[s];
                    au += us[k] * W2s[k * 68 + c];
                    av += vbs[k] * W2s[k * 68 + c];
                    d_tab[(hs * 65 + s) * 68 + c] = __float22half2_rn(make_float2(au, av));
                }
            }
        }
    } else {
        // block 8: p/q/r/t + fa weight packing
        __shared__ float sp[4], sq[4], sr[4], st[4];
        if (tid < 4) { sp[tid] = 0.f; sq[tid] = 0.f; sr[tid] = 0.f; st[tid] = 0.f; }
        __syncthreads();
        {
            float u = 0.f, v = 0.f;
            for (int k = 0; k < 64; k++) {
                float w1 = W1[k * 256 + tid];
                u += Win[k] * w1;
                v += bin[k] * w1;
            }
            int hh = tid >> 6;
            float as_ = a1s[tid], ad_ = a1d[tid];
            atomicAdd(&sp[hh], u * as_);
            atomicAdd(&sq[hh], v * as_);
            atomicAdd(&sr[hh], u * ad_);
            atomicAdd(&st[hh], v * ad_);
        }
        __syncthreads();
        if (tid < 4) { d_p[tid] = sp[tid]; d_q[tid] = sq[tid]; d_r[tid] = sr[tid]; d_t[tid] = st[tid]; }
        for (int idx = tid; idx < 64 * 32; idx += 256) {
            int c = idx >> 5, k = idx & 31;
            d_faW1h[idx] = __floats2half2_rn(faW1[c * 64 + 2 * k], faW1[c * 64 + 2 * k + 1]);
        }
        if (tid < 32) {
            d_fab1h[tid] = __floats2half2_rn(fab1[2 * tid], fab1[2 * tid + 1]);
            d_faW2h[tid] = __floats2half2_rn(faW2[2 * tid], faW2[2 * tid + 1]);
        }
    }
}

// ---------------- GAT-1 edge pass (real edges only; S0/S1 pre-zeroed) ----------------
__global__ void gat1_k(const int* __restrict__ ei, const float* __restrict__ x) {
    int idx = blockIdx.x * 256 + threadIdx.x;
    int s = ei[idx], d = ei[EE + idx];
    float xs = __ldg(&x[s]);
    float xd = __ldg(&x[d]);
    float ex[4];
#pragma unroll
    for (int h = 0; h < 4; h++) {
        float e = xs * d_p[h] + d_q[h] + xd * d_r[h] + d_t[h];
        e = (e > 0.f) ? e : 0.2f * e;
        ex[h] = __expf(e);
    }
    atomicAdd(&d_S0[d], make_float4(ex[0], ex[1], ex[2], ex[3]));
    atomicAdd(&d_S1[d], make_float4(ex[0] * xs, ex[1] * xs, ex[2] * xs, ex[3] * xs));
}

// ---------------- piecewise-linear "GEMM" with tables in shared + both self-loops ----------------
// 128 blocks x 1024 threads; each block loads the full table (143KB) into shared,
// each warp handles 16 consecutive nodes.
__global__ void g2_k(const float* __restrict__ x) {
    extern __shared__ __align__(16) char smem[];
    __half2* tabS = (__half2*)smem;
    float* thrS = (float*)(smem + TAB_BYTES);
    int tid = threadIdx.x;  // 1024
    {
        const uint4* src = (const uint4*)d_tab;
        uint4* dst = (uint4*)tabS;
        for (int i = tid; i < TAB_BYTES / 16; i += 1024) dst[i] = src[i];
        for (int i = tid; i < 512; i += 1024) thrS[i] = d_thr[i];
    }
    __syncthreads();
    int lane = tid & 31, w = tid >> 5;
    int node0 = blockIdx.x * 512 + w * 16;
    float pr = 0.f, qt = 0.f;
    if (lane < 4) { pr = d_p[lane] + d_r[lane]; qt = d_q[lane] + d_t[lane]; }
    for (int ni = 0; ni < 16; ni++) {
        int node = node0 + ni;
        float4 s0 = d_S0[node], s1 = d_S1[node];
        float xn = __ldg(&x[node]);
        // layer-1 self-loop contribution
        float exl = 0.f;
        if (lane < 4) {
            float e = xn * pr + qt;
            e = (e > 0.f) ? e : 0.2f * e;
            exl = __expf(e);
        }
        float e0 = __shfl_sync(0xffffffffu, exl, 0);
        float e1 = __shfl_sync(0xffffffffu, exl, 1);
        float e2 = __shfl_sync(0xffffffffu, exl, 2);
        float e3 = __shfl_sync(0xffffffffu, exl, 3);
        s0.x += e0; s0.y += e1; s0.z += e2; s0.w += e3;
        s1.x += e0 * xn; s1.y += e1 * xn; s1.z += e2 * xn; s1.w += e3 * xn;
        float wh[4] = { s1.x / s0.x, s1.y / s0.y, s1.z / s0.z, s1.w / s0.w };
        float acc0 = 0.f, acc1 = 0.f, acc2 = 0.f;
#pragma unroll
        for (int hs = 0; hs < 8; hs++) {
            float wv = wh[hs >> 1];
            float t0 = thrS[hs * 64 + lane];
            float t1 = thrS[hs * 64 + 32 + lane];
            bool p0, p1;
            if ((hs & 1) == 0) { p0 = t0 < wv;  p1 = t1 < wv; }
            else               { p0 = t0 <= wv; p1 = t1 <= wv; }
            int cnt = __popc(__ballot_sync(0xffffffffu, p0)) +
                      __popc(__ballot_sync(0xffffffffu, p1));
            const __half2* ptr = &tabS[(hs * 65 + cnt) * 68];
            uint2 tp = *(const uint2*)&ptr[2 * lane];
            float2 f0 = __half22float2(*(__half2*)&tp.x);
            float2 f1 = __half22float2(*(__half2*)&tp.y);
            acc0 += wv * f0.x + f0.y;
            acc1 += wv * f1.x + f1.y;
            if (lane < 2) {
                float2 f2 = __half22float2(ptr[64 + lane]);
                acc2 += wv * f2.x + f2.y;
            }
        }
        d_gh[node * 32 + lane] = __floats2half2_rn(acc0, acc1);
        if (lane == 0) d_a2s[node] = acc2;
        if (lane == 1) d_a2d[node] = acc2;
        // GAT-2 self-loop init
        float a2s_n = __shfl_sync(0xffffffffu, acc2, 0);
        float a2d_n = __shfl_sync(0xffffffffu, acc2, 1);
        float el = a2s_n + a2d_n;
        el = (el > 0.f) ? el : 0.2f * el;
        float exs = __expf(el);
        d_out2h[node * 32 + lane] = __floats2half2_rn(exs * acc0, exs * acc1);
        if (lane == 0) d_den2[node] = exs;
    }
}

// ---------------- GAT-2 edge pass: two-phase, fp16 v4.f16x2 REDs ----------------
__global__ void gat2_k(const int* __restrict__ ei) {
    __shared__ int sS[512];
    __shared__ int sD[512];
    __shared__ float sEx[512];
    int tid = threadIdx.x;
    int e0 = blockIdx.x * 512;
#pragma unroll
    for (int k = 0; k < 2; k++) {
        int i = tid + k * 256;
        int e = e0 + i;
        int s = __ldg(&ei[e]);
        int d = __ldg(&ei[EE + e]);
        float el = __ldg(&d_a2s[s]) + __ldg(&d_a2d[d]);
        el = (el > 0.f) ? el : 0.2f * el;
        float ex = __expf(el);
        sS[i] = s; sD[i] = d; sEx[i] = ex;
        atomicAdd(&d_den2[d], ex);
    }
    __syncthreads();
    int l = tid & 7, grp = tid >> 3;
    int base = grp * 16;
#pragma unroll 4
    for (int j = 0; j < 16; j++) {
        int i = base + j;
        int s = sS[i];
        int d = sD[i];
        float ex = sEx[i];
        uint4 gp = *(const uint4*)&d_gh[s * 32 + l * 4];
        float2 a0 = __half22float2(*(__half2*)&gp.x);
        float2 a1 = __half22float2(*(__half2*)&gp.y);
        float2 a2 = __half22float2(*(__half2*)&gp.z);
        float2 a3 = __half22float2(*(__half2*)&gp.w);
        unsigned r0 = pack_h2(ex * a0.x, ex * a0.y);
        unsigned r1 = pack_h2(ex * a1.x, ex * a1.y);
        unsigned r2 = pack_h2(ex * a2.x, ex * a2.y);
        unsigned r3 = pack_h2(ex * a3.x, ex * a3.y);
        asm volatile("red.global.add.noftz.v4.f16x2 [%0], {%1, %2, %3, %4};"
                     :: "l"(&d_out2h[d * 32 + l * 4]),
                        "r"(r0), "r"(r1), "r"(r2), "r"(r3)
                     : "memory");
    }
}

// ---------------- fused: h2 finalize + pooling + feature attention + (last block) classifier ----------------
__global__ void att_k(const float* __restrict__ b2, const float* __restrict__ fab2,
                      const float* __restrict__ clsW, const float* __restrict__ clsb,
                      float* __restrict__ out) {
    __shared__ __align__(16) __half2 W1s[64 * 32];
    __shared__ __half2 b1s[32], w2s[32];
    __shared__ float b2s[64];
    __shared__ float fas[64];
    __shared__ int lastS;
    int tid = threadIdx.x;  // 128
    for (int i = tid; i < 2048; i += 128) W1s[i] = d_faW1h[i];
    if (tid < 32) { b1s[tid] = d_fab1h[tid]; w2s[tid] = d_faW2h[tid]; }
    if (tid < 64) { b2s[tid] = b2[tid]; fas[tid] = 0.f; }
    __syncthreads();
    int n = blockIdx.x * 128 + tid;
    int bg = n >> 6;
    float inv = 1.f / d_den2[n];
    __half2 hh[32];
#pragma unroll
    for (int i = 0; i < 8; i++) {
        uint4 o4 = *(const uint4*)&d_out2h[n * 32 + i * 4];
        float2 f0 = __half22float2(*(__half2*)&o4.x);
        float2 f1 = __half22float2(*(__half2*)&o4.y);
        float2 f2 = __half22float2(*(__half2*)&o4.z);
        float2 f3 = __half22float2(*(__half2*)&o4.w);
        float4 h0, h1;
        h0.x = fmaxf(f0.x * inv + b2s[i * 8 + 0], 0.f);
        h0.y = fmaxf(f0.y * inv + b2s[i * 8 + 1], 0.f);
        h0.z = fmaxf(f1.x * inv + b2s[i * 8 + 2], 0.f);
        h0.w = fmaxf(f1.y * inv + b2s[i * 8 + 3], 0.f);
        h1.x = fmaxf(f2.x * inv + b2s[i * 8 + 4], 0.f);
        h1.y = fmaxf(f2.y * inv + b2s[i * 8 + 5], 0.f);
        h1.z = fmaxf(f3.x * inv + b2s[i * 8 + 6], 0.f);
        h1.w = fmaxf(f3.y * inv + b2s[i * 8 + 7], 0.f);
        atomicAdd((float4*)&d_pool[bg * 64 + i * 8], h0);
        atomicAdd((float4*)&d_pool[bg * 64 + i * 8 + 4], h1);
        hh[i * 4 + 0] = __floats2half2_rn(h0.x, h0.y);
        hh[i * 4 + 1] = __floats2half2_rn(h0.z, h0.w);
        hh[i * 4 + 2] = __floats2half2_rn(h1.x, h1.y);
        hh[i * 4 + 3] = __floats2half2_rn(h1.z, h1.w);
    }
    __half2 acc[32];
#pragma unroll
    for (int i = 0; i < 32; i++) acc[i] = b1s[i];
#pragma unroll
    for (int ci = 0; ci < 32; ci++) {
        __half2 hc0 = __low2half2(hh[ci]);
        __half2 hc1 = __high2half2(hh[ci]);
        const uint4* wr0 = (const uint4*)&W1s[(2 * ci) * 32];
        const uint4* wr1 = (const uint4*)&W1s[(2 * ci + 1) * 32];
#pragma unroll
        for (int i = 0; i < 8; i++) {
            uint4 w0 = wr0[i];
            acc[i * 4 + 0] = __hfma2(hc0, *(__half2*)&w0.x, acc[i * 4 + 0]);
            acc[i * 4 + 1] = __hfma2(hc0, *(__half2*)&w0.y, acc[i * 4 + 1]);
            acc[i * 4 + 2] = __hfma2(hc0, *(__half2*)&w0.z, acc[i * 4 + 2]);
            acc[i * 4 + 3] = __hfma2(hc0, *(__half2*)&w0.w, acc[i * 4 + 3]);
        }
#pragma unroll
        for (int i = 0; i < 8; i++) {
            uint4 w1 = wr1[i];
            acc[i * 4 + 0] = __hfma2(hc1, *(__half2*)&w1.x, acc[i * 4 + 0]);
            acc[i * 4 + 1] = __hfma2(hc1, *(__half2*)&w1.y, acc[i * 4 + 1]);
            acc[i * 4 + 2] = __hfma2(hc1, *(__half2*)&w1.z, acc[i * 4 + 2]);
            acc[i * 4 + 3] = __hfma2(hc1, *(__half2*)&w1.w, acc[i * 4 + 3]);
        }
    }
    __half2 zero2 = __float2half2_rn(0.f);
    __half2 rs = zero2;
#pragma unroll
    for (int i = 0; i < 32; i++)
        rs = __hfma2(__hmax2(acc[i], zero2), w2s[i], rs);
    float res = fab2[0] + __low2float(rs) + __high2float(rs);
    float att = 1.f / (1.f + __expf(-res));
    atomicAdd(&fas[n & 63], att);
    __syncthreads();
    if (tid < 64) atomicAdd(&d_fa[tid], fas[tid]);
    // self-clean S0/S1 for the next call (dead after g2_k)
    d_S0[n] = make_float4(0.f, 0.f, 0.f, 0.f);
    d_S1[n] = make_float4(0.f, 0.f, 0.f, 0.f);
    __threadfence();
    if (tid == 0) lastS = atomicAdd(&d_ctr, 1);
    __syncthreads();
    if (lastS == gridDim.x - 1) {
        __threadfence();
        // classifier: 128 threads x 8 graphs
        const float pinv = 1.f / (float)FEATN;
        for (int g = tid; g < BB; g += 128) {
            float p[64];
#pragma unroll
            for (int i = 0; i < 16; i++) {
                float4 v = *(const float4*)&d_pool[g * 64 + i * 4];
                p[i * 4] = v.x * pinv; p[i * 4 + 1] = v.y * pinv;
                p[i * 4 + 2] = v.z * pinv; p[i * 4 + 3] = v.w * pinv;
            }
#pragma unroll
            for (int j = 0; j < NCLS; j++) {
                float o = clsb[j];
#pragma unroll
                for (int c = 0; c < 64; c++) o += p[c] * clsW[c * NCLS + j];
                out[g * NCLS + j] = o;
            }
        }
        if (tid < 64) {
            out[BB * NCLS + tid] = d_fa[tid] * (1.f / (float)BB);
        }
        __syncthreads();
        // self-clean pool/fa/ctr for the next call
        if (tid < 64) d_fa[tid] = 0.f;
        float4 z4 = make_float4(0.f, 0.f, 0.f, 0.f);
        for (int i = tid; i < BB * 16; i += 128) ((float4*)d_pool)[i] = z4;
        __syncthreads();
        if (tid == 0) d_ctr = 0;
    }
}

extern "C" void kernel_launch(void* const* d_in, const int* in_sizes, int n_in,
                              void* d_out, int out_size) {
    const float* x    = (const float*)d_in[0];
    const int*   ei   = (const int*)d_in[1];
    const float* Win  = (const float*)d_in[3];
    const float* bin  = (const float*)d_in[4];
    const float* W1   = (const float*)d_in[5];
    const float* a1s  = (const float*)d_in[6];
    const float* a1d  = (const float*)d_in[7];
    const float* b1   = (const float*)d_in[8];
    const float* W2   = (const float*)d_in[9];
    const float* a2s  = (const float*)d_in[10];
    const float* a2d  = (const float*)d_in[11];
    const float* b2   = (const float*)d_in[12];
    const float* faW1 = (const float*)d_in[13];
    const float* fab1 = (const float*)d_in[14];
    const float* faW2 = (const float*)d_in[15];
    const float* fab2 = (const float*)d_in[16];
    const float* clsW = (const float*)d_in[17];
    const float* clsb = (const float*)d_in[18];
    float* out = (float*)d_out;

    cudaFuncSetAttribute(g2_k, cudaFuncAttributeMaxDynamicSharedMemorySize, G2_SMEM);

    prep_k<<<9, 256>>>(Win, bin, W1, a1s, a1d, b1, W2, a2s, a2d, faW1, fab1, faW2);
    gat1_k<<<EE / 256, 256>>>(ei, x);
    g2_k<<<NN / 512, 1024, G2_SMEM>>>(x);
    gat2_k<<<EE / 512, 256>>>(ei);
    att_k<<<NN / 128, 128>>>(b2, fab2, clsW, clsb, out);
}

// round 14
// speedup vs baseline: 1.0454x; 1.0454x over previous
#include <cuda_runtime.h>
#include <cuda_fp16.h>

#define NN 65536
#define EE 524288
#define BB 1024
#define FEATN 64
#define NCLS 5
#define INF_F __int_as_float(0x7f800000)

// ---------------- scratch (device globals; no allocs allowed) ----------------
__device__ float d_p[4], d_q[4], d_r[4], d_t[4];
__device__ __align__(16) float4 d_S0[NN];
__device__ __align__(16) float4 d_S1[NN];
__device__ __align__(16) __half2 d_gh[NN * 32];      // g rows, fp16
__device__ float d_a2s[NN];
__device__ float d_a2d[NN];
__device__ float d_den2[NN];
__device__ __align__(16) __half2 d_out2h[NN * 32];   // gat2 numerator, fp16 (init in g2_k)
__device__ __align__(16) float d_pool[BB * 64];
__device__ float d_fa[64];
__device__ int d_ctr;                                 // zero-init; self-resets each call
// piecewise-linear GEMM tables (half precision)
__device__ float d_thr[8 * 64];
__device__ __align__(16) __half2 d_tab[8 * 65 * 68];
// feature-attention weights, half2-packed
__device__ __align__(16) __half2 d_faW1h[64 * 32];
__device__ __align__(8)  __half2 d_fab1h[32];
__device__ __align__(8)  __half2 d_faW2h[32];

__device__ __forceinline__ unsigned pack_h2(float a, float b) {
    __half2 h = __floats2half2_rn(a, b);
    return *(unsigned*)&h;
}

// ---------------- fused init: tables + self-loop S0/S1 + zeroing + weight packing ----------------
__global__ void init_k(const float* __restrict__ x,
                       const float* __restrict__ Win, const float* __restrict__ bin,
                       const float* __restrict__ W1, const float* __restrict__ a1s,
                       const float* __restrict__ a1d, const float* __restrict__ b1,
                       const float* __restrict__ W2, const float* __restrict__ a2sv,
                       const float* __restrict__ a2dv, const float* __restrict__ faW1,
                       const float* __restrict__ fab1, const float* __restrict__ faW2) {
    int b = blockIdx.x;
    int tid = threadIdx.x;      // 256
    if (b < 8) {
        int hs = b, h = hs >> 1, set = hs & 1;
        __shared__ float W2s[64 * 68];
        __shared__ float us[64], vbs[64], key[64];
        __shared__ int sidx[64];
        __shared__ unsigned char memb[64];
        __shared__ int n_s;
        if (tid < 64) {
            float u = 0.f, v = 0.f;
            for (int k = 0; k < 64; k++) {
                float w1 = W1[k * 256 + h * 64 + tid];
                u += Win[k] * w1;
                v += bin[k] * w1;
            }
            float vb = v + b1[h * 64 + tid];
            us[tid] = u; vbs[tid] = vb;
            bool m = (set == 0) ? (u > 0.f) : (u < 0.f);
            memb[tid] = m ? 1 : 0;
            key[tid] = m ? (-vb / u) : INF_F;
        }
        for (int i = tid; i < 64 * 64; i += 256) {
            int j = i >> 6, c = i & 63;
            W2s[j * 68 + c] = W2[(h * 64 + j) * 64 + c];
        }
        __syncthreads();
        if (tid < 64) {
            float as = 0.f, ad = 0.f;
            for (int c = 0; c < 64; c++) {
                float w2 = W2s[tid * 68 + c];
                as += w2 * a2sv[c];
                ad += w2 * a2dv[c];
            }
            W2s[tid * 68 + 64] = as;
            W2s[tid * 68 + 65] = ad;
            W2s[tid * 68 + 66] = 0.f;
            W2s[tid * 68 + 67] = 0.f;
        }
        __syncthreads();
        if (tid < 64) {
            float ki = key[tid];
            int r = 0;
            for (int j = 0; j < 64; j++) {
                float kj = key[j];
                r += (kj < ki) || (kj == ki && j < tid);
            }
            sidx[r] = tid;
        }
        if (tid == 0) {
            int n = 0;
            for (int j = 0; j < 64; j++) n += memb[j];
            n_s = n;
        }
        __syncthreads();
        int n = n_s;
        if (tid < 64) d_thr[hs * 64 + tid] = key[sidx[tid]];
        if (tid < 68) {
            int c = tid;
            if (set == 0) {
                float base = 0.f;
                for (int j = 0; j < 64; j++)
                    if (us[j] == 0.f && vbs[j] > 0.f) base += vbs[j] * W2s[j * 68 + c];
                float au = 0.f, av = base;
                d_tab[(hs * 65 + 0) * 68 + c] = __float22half2_rn(make_float2(au, av));
                for (int s = 0; s < 64; s++) {
                    if (s < n) {
                        int k = sidx[s];
                        au += us[k] * W2s[k * 68 + c];
                        av += vbs[k] * W2s[k * 68 + c];
                    }
                    d_tab[(hs * 65 + s + 1) * 68 + c] = __float22half2_rn(make_float2(au, av));
                }
            } else {
                for (int s = n; s <= 64; s++)
                    d_tab[(hs * 65 + s) * 68 + c] = __float22half2_rn(make_float2(0.f, 0.f));
                float au = 0.f, av = 0.f;
                for (int s = n - 1; s >= 0; s--) {
                    int k = sidx[s];
                    au += us[k] * W2s[k * 68 + c];
                    av += vbs[k] * W2s[k * 68 + c];
                    d_tab[(hs * 65 + s) * 68 + c] = __float22half2_rn(make_float2(au, av));
                }
            }
        }
    } else {
        __shared__ float sp[4], sq[4], sr[4], st[4];
        if (tid < 4) { sp[tid] = 0.f; sq[tid] = 0.f; sr[tid] = 0.f; st[tid] = 0.f; }
        __syncthreads();
        {
            float u = 0.f, v = 0.f;
            for (int k = 0; k < 64; k++) {
                float w1 = W1[k * 256 + tid];
                u += Win[k] * w1;
                v += bin[k] * w1;
            }
            int hh = tid >> 6;
            float as_ = a1s[tid], ad_ = a1d[tid];
            atomicAdd(&sp[hh], u * as_);
            atomicAdd(&sq[hh], v * as_);
            atomicAdd(&sr[hh], u * ad_);
            atomicAdd(&st[hh], v * ad_);
        }
        __syncthreads();
        if (b == 8) {
            if (tid < 4) { d_p[tid] = sp[tid]; d_q[tid] = sq[tid]; d_r[tid] = sr[tid]; d_t[tid] = st[tid]; }
            for (int idx = tid; idx < 64 * 32; idx += 256) {
                int c = idx >> 5, k = idx & 31;
                d_faW1h[idx] = __floats2half2_rn(faW1[c * 64 + 2 * k], faW1[c * 64 + 2 * k + 1]);
            }
            if (tid < 32) {
                d_fab1h[tid] = __floats2half2_rn(fab1[2 * tid], fab1[2 * tid + 1]);
                d_faW2h[tid] = __floats2half2_rn(faW2[2 * tid], faW2[2 * tid + 1]);
            }
            if (tid < 64) d_fa[tid] = 0.f;
        }
        float pr[4], qt[4];
#pragma unroll
        for (int h = 0; h < 4; h++) { pr[h] = sp[h] + sr[h]; qt[h] = sq[h] + st[h]; }
        int i0 = (b - 8) * 256 + tid;
        int stride = 152 * 256;
        for (int nn = i0; nn < NN; nn += stride) {
            float xn = __ldg(&x[nn]);
            float ex[4];
#pragma unroll
            for (int h = 0; h < 4; h++) {
                float e = xn * pr[h] + qt[h];
                e = (e > 0.f) ? e : 0.2f * e;
                ex[h] = __expf(e);
            }
            d_S0[nn] = make_float4(ex[0], ex[1], ex[2], ex[3]);
            d_S1[nn] = make_float4(ex[0] * xn, ex[1] * xn, ex[2] * xn, ex[3] * xn);
        }
        for (int i = i0; i < BB * 64; i += stride) d_pool[i] = 0.f;
    }
}

// ---------------- GAT-1 edge pass (real edges only): accumulate S0 and S1 ----------------
__global__ void gat1_k(const int* __restrict__ ei, const float* __restrict__ x) {
    int idx = blockIdx.x * 256 + threadIdx.x;
    int s = ei[idx], d = ei[EE + idx];
    float xs = __ldg(&x[s]);
    float xd = __ldg(&x[d]);
    float ex[4];
#pragma unroll
    for (int h = 0; h < 4; h++) {
        float e = xs * d_p[h] + d_q[h] + xd * d_r[h] + d_t[h];
        e = (e > 0.f) ? e : 0.2f * e;
        ex[h] = __expf(e);
    }
    atomicAdd(&d_S0[d], make_float4(ex[0], ex[1], ex[2], ex[3]));
    atomicAdd(&d_S1[d], make_float4(ex[0] * xs, ex[1] * xs, ex[2] * xs, ex[3] * xs));
}

// ---------------- piecewise-linear "GEMM" + GAT-2 self-loop init (half2) ----------------
__global__ void g2_k() {
    __shared__ float thrS[8 * 64];
    int tid = threadIdx.x;  // 256
    for (int i = tid; i < 512; i += 256) thrS[i] = d_thr[i];
    __syncthreads();
    int lane = tid & 31, w = tid >> 5;
    int node = blockIdx.x * 8 + w;
    float4 s0 = d_S0[node], s1 = d_S1[node];
    float wh[4] = { s1.x / s0.x, s1.y / s0.y, s1.z / s0.z, s1.w / s0.w };
    float acc0 = 0.f, acc1 = 0.f, acc2 = 0.f;
#pragma unroll
    for (int hs = 0; hs < 8; hs++) {
        float wv = wh[hs >> 1];
        float t0 = thrS[hs * 64 + lane];
        float t1 = thrS[hs * 64 + 32 + lane];
        bool p0, p1;
        if ((hs & 1) == 0) { p0 = t0 < wv;  p1 = t1 < wv; }
        else               { p0 = t0 <= wv; p1 = t1 <= wv; }
        int cnt = __popc(__ballot_sync(0xffffffffu, p0)) +
                  __popc(__ballot_sync(0xffffffffu, p1));
        const __half2* ptr = &d_tab[(hs * 65 + cnt) * 68];
        uint2 tp = *(const uint2*)&ptr[2 * lane];
        float2 e0 = __half22float2(*(__half2*)&tp.x);
        float2 e1 = __half22float2(*(__half2*)&tp.y);
        acc0 += wv * e0.x + e0.y;
        acc1 += wv * e1.x + e1.y;
        if (lane < 2) {
            float2 e2 = __half22float2(__ldg(&ptr[64 + lane]));
            acc2 += wv * e2.x + e2.y;
        }
    }
    d_gh[node * 32 + lane] = __floats2half2_rn(acc0, acc1);
    if (lane == 0) d_a2s[node] = acc2;
    if (lane == 1) d_a2d[node] = acc2;
    float a2s_n = __shfl_sync(0xffffffffu, acc2, 0);
    float a2d_n = __shfl_sync(0xffffffffu, acc2, 1);
    float el = a2s_n + a2d_n;
    el = (el > 0.f) ? el : 0.2f * el;
    float exs = __expf(el);
    d_out2h[node * 32 + lane] = __floats2half2_rn(exs * acc0, exs * acc1);
    if (lane == 0) d_den2[node] = exs;
}

// ---------------- GAT-2 edge pass: two-phase, fp16 v4.f16x2 REDs (8 lanes/edge) ----------------
__global__ void gat2_k(const int* __restrict__ ei) {
    __shared__ int sS[512];
    __shared__ int sD[512];
    __shared__ float sEx[512];
    int tid = threadIdx.x;
    int e0 = blockIdx.x * 512;
#pragma unroll
    for (int k = 0; k < 2; k++) {
        int i = tid + k * 256;
        int e = e0 + i;
        int s = __ldg(&ei[e]);
        int d = __ldg(&ei[EE + e]);
        float el = __ldg(&d_a2s[s]) + __ldg(&d_a2d[d]);
        el = (el > 0.f) ? el : 0.2f * el;
        float ex = __expf(el);
        sS[i] = s; sD[i] = d; sEx[i] = ex;
        atomicAdd(&d_den2[d], ex);
    }
    __syncthreads();
    int l = tid & 7, grp = tid >> 3;     // 32 groups x 8 lanes
    int base = grp * 16;
#pragma unroll 4
    for (int j = 0; j < 16; j++) {
        int i = base + j;
        int s = sS[i];
        int d = sD[i];
        float ex = sEx[i];
        uint4 gp = *(const uint4*)&d_gh[s * 32 + l * 4];
        float2 a0 = __half22float2(*(__half2*)&gp.x);
        float2 a1 = __half22float2(*(__half2*)&gp.y);
        float2 a2 = __half22float2(*(__half2*)&gp.z);
        float2 a3 = __half22float2(*(__half2*)&gp.w);
        unsigned r0 = pack_h2(ex * a0.x, ex * a0.y);
        unsigned r1 = pack_h2(ex * a1.x, ex * a1.y);
        unsigned r2 = pack_h2(ex * a2.x, ex * a2.y);
        unsigned r3 = pack_h2(ex * a3.x, ex * a3.y);
        asm volatile("red.global.add.noftz.v4.f16x2 [%0], {%1, %2, %3, %4};"
                     :: "l"(&d_out2h[d * 32 + l * 4]),
                        "r"(r0), "r"(r1), "r"(r2), "r"(r3)
                     : "memory");
    }
}

// ---------------- fused: h2 finalize + pooling + feature attention + last-block classifier ----------------
__global__ void att_k(const float* __restrict__ b2, const float* __restrict__ fab2,
                      const float* __restrict__ clsW, const float* __restrict__ clsb,
                      float* __restrict__ out) {
    __shared__ __align__(16) __half2 W1s[64 * 32];
    __shared__ __half2 b1s[32], w2s[32];
    __shared__ float b2s[64];
    __shared__ float fas[64];
    __shared__ int lastS;
    int tid = threadIdx.x;  // 128
    for (int i = tid; i < 2048; i += 128) W1s[i] = d_faW1h[i];
    if (tid < 32) { b1s[tid] = d_fab1h[tid]; w2s[tid] = d_faW2h[tid]; }
    if (tid < 64) { b2s[tid] = b2[tid]; fas[tid] = 0.f; }
    __syncthreads();
    int n = blockIdx.x * 128 + tid;
    int bg = n >> 6;
    float inv = 1.f / d_den2[n];
    __half2 hh[32];
#pragma unroll
    for (int i = 0; i < 8; i++) {
        uint4 o4 = *(const uint4*)&d_out2h[n * 32 + i * 4];
        float2 f0 = __half22float2(*(__half2*)&o4.x);
        float2 f1 = __half22float2(*(__half2*)&o4.y);
        float2 f2 = __half22float2(*(__half2*)&o4.z);
        float2 f3 = __half22float2(*(__half2*)&o4.w);
        float4 h0, h1;
        h0.x = fmaxf(f0.x * inv + b2s[i * 8 + 0], 0.f);
        h0.y = fmaxf(f0.y * inv + b2s[i * 8 + 1], 0.f);
        h0.z = fmaxf(f1.x * inv + b2s[i * 8 + 2], 0.f);
        h0.w = fmaxf(f1.y * inv + b2s[i * 8 + 3], 0.f);
        h1.x = fmaxf(f2.x * inv + b2s[i * 8 + 4], 0.f);
        h1.y = fmaxf(f2.y * inv + b2s[i * 8 + 5], 0.f);
        h1.z = fmaxf(f3.x * inv + b2s[i * 8 + 6], 0.f);
        h1.w = fmaxf(f3.y * inv + b2s[i * 8 + 7], 0.f);
        atomicAdd((float4*)&d_pool[bg * 64 + i * 8], h0);
        atomicAdd((float4*)&d_pool[bg * 64 + i * 8 + 4], h1);
        hh[i * 4 + 0] = __floats2half2_rn(h0.x, h0.y);
        hh[i * 4 + 1] = __floats2half2_rn(h0.z, h0.w);
        hh[i * 4 + 2] = __floats2half2_rn(h1.x, h1.y);
        hh[i * 4 + 3] = __floats2half2_rn(h1.z, h1.w);
    }
    __half2 acc[32];
#pragma unroll
    for (int i = 0; i < 32; i++) acc[i] = b1s[i];
#pragma unroll
    for (int ci = 0; ci < 32; ci++) {
        __half2 hc0 = __low2half2(hh[ci]);
        __half2 hc1 = __high2half2(hh[ci]);
        const uint4* wr0 = (const uint4*)&W1s[(2 * ci) * 32];
        const uint4* wr1 = (const uint4*)&W1s[(2 * ci + 1) * 32];
#pragma unroll
        for (int i = 0; i < 8; i++) {
            uint4 w0 = wr0[i];
            acc[i * 4 + 0] = __hfma2(hc0, *(__half2*)&w0.x, acc[i * 4 + 0]);
            acc[i * 4 + 1] = __hfma2(hc0, *(__half2*)&w0.y, acc[i * 4 + 1]);
            acc[i * 4 + 2] = __hfma2(hc0, *(__half2*)&w0.z, acc[i * 4 + 2]);
            acc[i * 4 + 3] = __hfma2(hc0, *(__half2*)&w0.w, acc[i * 4 + 3]);
        }
#pragma unroll
        for (int i = 0; i < 8; i++) {
            uint4 w1 = wr1[i];
            acc[i * 4 + 0] = __hfma2(hc1, *(__half2*)&w1.x, acc[i * 4 + 0]);
            acc[i * 4 + 1] = __hfma2(hc1, *(__half2*)&w1.y, acc[i * 4 + 1]);
            acc[i * 4 + 2] = __hfma2(hc1, *(__half2*)&w1.z, acc[i * 4 + 2]);
            acc[i * 4 + 3] = __hfma2(hc1, *(__half2*)&w1.w, acc[i * 4 + 3]);
        }
    }
    __half2 zero2 = __float2half2_rn(0.f);
    __half2 rs = zero2;
#pragma unroll
    for (int i = 0; i < 32; i++)
        rs = __hfma2(__hmax2(acc[i], zero2), w2s[i], rs);
    float res = fab2[0] + __low2float(rs) + __high2float(rs);
    float att = 1.f / (1.f + __expf(-res));
    atomicAdd(&fas[n & 63], att);
    __syncthreads();
    if (tid < 64) atomicAdd(&d_fa[tid], fas[tid]);
    __threadfence();
    __syncthreads();
    if (tid == 0) lastS = atomicAdd(&d_ctr, 1);
    __syncthreads();
    if (lastS == (int)gridDim.x - 1) {
        __threadfence();
        const float pinv = 1.f / (float)FEATN;
        for (int g = tid; g < BB; g += 128) {
            float p[64];
#pragma unroll
            for (int i = 0; i < 16; i++) {
                float4 v = *(const float4*)&d_pool[g * 64 + i * 4];
                p[i * 4] = v.x * pinv; p[i * 4 + 1] = v.y * pinv;
                p[i * 4 + 2] = v.z * pinv; p[i * 4 + 3] = v.w * pinv;
            }
#pragma unroll
            for (int j = 0; j < NCLS; j++) {
                float o = clsb[j];
#pragma unroll
                for (int c = 0; c < 64; c++) o += p[c] * clsW[c * NCLS + j];
                out[g * NCLS + j] = o;
            }
        }
        if (tid < 64) out[BB * NCLS + tid] = d_fa[tid] * (1.f / (float)BB);
        __syncthreads();
        if (tid == 0) d_ctr = 0;   // self-reset for next call / replay
    }
}

extern "C" void kernel_launch(void* const* d_in, const int* in_sizes, int n_in,
                              void* d_out, int out_size) {
    const float* x    = (const float*)d_in[0];
    const int*   ei   = (const int*)d_in[1];
    const float* Win  = (const float*)d_in[3];
    const float* bin  = (const float*)d_in[4];
    const float* W1   = (const float*)d_in[5];
    const float* a1s  = (const float*)d_in[6];
    const float* a1d  = (const float*)d_in[7];
    const float* b1   = (const float*)d_in[8];
    const float* W2   = (const float*)d_in[9];
    const float* a2s  = (const float*)d_in[10];
    const float* a2d  = (const float*)d_in[11];
    const float* b2   = (const float*)d_in[12];
    const float* faW1 = (const float*)d_in[13];
    const float* fab1 = (const float*)d_in[14];
    const float* faW2 = (const float*)d_in[15];
    const float* fab2 = (const float*)d_in[16];
    const float* clsW = (const float*)d_in[17];
    const float* clsb = (const float*)d_in[18];
    float* out = (float*)d_out;

    init_k<<<160, 256>>>(x, Win, bin, W1, a1s, a1d, b1, W2, a2s, a2d, faW1, fab1, faW2);
    gat1_k<<<EE / 256, 256>>>(ei, x);
    g2_k<<<NN / 8, 256>>>();
    gat2_k<<<EE / 512, 256>>>(ei);
    att_k<<<NN / 128, 128>>>(b2, fab2, clsW, clsb, out);
}

// round 15
// speedup vs baseline: 1.0625x; 1.0164x over previous
#include <cuda_runtime.h>
#include <cuda_fp16.h>

#define NN 65536
#define EE 524288
#define BB 1024
#define FEATN 64
#define NCLS 5
#define INF_F __int_as_float(0x7f800000)

// ---------------- scratch (device globals; no allocs allowed) ----------------
__device__ float d_p[4], d_q[4], d_r[4], d_t[4];
__device__ __align__(16) float4 d_S0[NN];
__device__ __align__(16) float4 d_S1[NN];
__device__ __align__(16) __half2 d_gh[NN * 32];      // g rows, fp16
__device__ float d_a2s[NN];
__device__ float d_a2d[NN];
__device__ float d_den2[NN];
__device__ __align__(16) __half2 d_out2h[NN * 32];   // gat2 numerator, fp16 (init in g2_k)
__device__ __align__(16) float d_pool[BB * 64];
__device__ float d_fa[64];
__device__ int d_ctr;                                 // zero-init; self-resets each call
// piecewise-linear GEMM tables (half precision)
__device__ float d_thr[8 * 64];
__device__ __align__(16) __half2 d_tab[8 * 65 * 68];
// feature-attention weights, half2-packed
__device__ __align__(16) __half2 d_faW1h[64 * 32];
__device__ __align__(8)  __half2 d_fab1h[32];
__device__ __align__(8)  __half2 d_faW2h[32];

__device__ __forceinline__ unsigned pack_h2(float a, float b) {
    __half2 h = __floats2half2_rn(a, b);
    return *(unsigned*)&h;
}

// ---------------- fused init: tables + self-loop S0/S1 + zeroing + weight packing ----------------
__global__ void init_k(const float* __restrict__ x,
                       const float* __restrict__ Win, const float* __restrict__ bin,
                       const float* __restrict__ W1, const float* __restrict__ a1s,
                       const float* __restrict__ a1d, const float* __restrict__ b1,
                       const float* __restrict__ W2, const float* __restrict__ a2sv,
                       const float* __restrict__ a2dv, const float* __restrict__ faW1,
                       const float* __restrict__ fab1, const float* __restrict__ faW2) {
    int b = blockIdx.x;
    int tid = threadIdx.x;      // 256
    if (b < 8) {
        int hs = b, h = hs >> 1, set = hs & 1;
        __shared__ float W2s[64 * 68];
        __shared__ float us[64], vbs[64], key[64];
        __shared__ int sidx[64];
        __shared__ unsigned char memb[64];
        __shared__ int n_s;
        if (tid < 64) {
            float u = 0.f, v = 0.f;
            for (int k = 0; k < 64; k++) {
                float w1 = W1[k * 256 + h * 64 + tid];
                u += Win[k] * w1;
                v += bin[k] * w1;
            }
            float vb = v + b1[h * 64 + tid];
            us[tid] = u; vbs[tid] = vb;
            bool m = (set == 0) ? (u > 0.f) : (u < 0.f);
            memb[tid] = m ? 1 : 0;
            key[tid] = m ? (-vb / u) : INF_F;
        }
        for (int i = tid; i < 64 * 64; i += 256) {
            int j = i >> 6, c = i & 63;
            W2s[j * 68 + c] = W2[(h * 64 + j) * 64 + c];
        }
        __syncthreads();
        if (tid < 64) {
            float as = 0.f, ad = 0.f;
            for (int c = 0; c < 64; c++) {
                float w2 = W2s[tid * 68 + c];
                as += w2 * a2sv[c];
                ad += w2 * a2dv[c];
            }
            W2s[tid * 68 + 64] = as;
            W2s[tid * 68 + 65] = ad;
            W2s[tid * 68 + 66] = 0.f;
            W2s[tid * 68 + 67] = 0.f;
        }
        __syncthreads();
        if (tid < 64) {
            float ki = key[tid];
            int r = 0;
            for (int j = 0; j < 64; j++) {
                float kj = key[j];
                r += (kj < ki) || (kj == ki && j < tid);
            }
            sidx[r] = tid;
        }
        if (tid == 0) {
            int n = 0;
            for (int j = 0; j < 64; j++) n += memb[j];
            n_s = n;
        }
        __syncthreads();
        int n = n_s;
        if (tid < 64) d_thr[hs * 64 + tid] = key[sidx[tid]];
        if (tid < 68) {
            int c = tid;
            if (set == 0) {
                float base = 0.f;
                for (int j = 0; j < 64; j++)
                    if (us[j] == 0.f && vbs[j] > 0.f) base += vbs[j] * W2s[j * 68 + c];
                float au = 0.f, av = base;
                d_tab[(hs * 65 + 0) * 68 + c] = __float22half2_rn(make_float2(au, av));
                for (int s = 0; s < 64; s++) {
                    if (s < n) {
                        int k = sidx[s];
                        au += us[k] * W2s[k * 68 + c];
                        av += vbs[k] * W2s[k * 68 + c];
                    }
                    d_tab[(hs * 65 + s + 1) * 68 + c] = __float22half2_rn(make_float2(au, av));
                }
            } else {
                for (int s = n; s <= 64; s++)
                    d_tab[(hs * 65 + s) * 68 + c] = __float22half2_rn(make_float2(0.f, 0.f));
                float au = 0.f, av = 0.f;
                for (int s = n - 1; s >= 0; s--) {
                    int k = sidx[s];
                    au += us[k] * W2s[k * 68 + c];
                    av += vbs[k] * W2s[k * 68 + c];
                    d_tab[(hs * 65 + s) * 68 + c] = __float22half2_rn(make_float2(au, av));
                }
            }
        }
    } else {
        __shared__ float sp[4], sq[4], sr[4], st[4];
        if (tid < 4) { sp[tid] = 0.f; sq[tid] = 0.f; sr[tid] = 0.f; st[tid] = 0.f; }
        __syncthreads();
        {
            float u = 0.f, v = 0.f;
            for (int k = 0; k < 64; k++) {
                float w1 = W1[k * 256 + tid];
                u += Win[k] * w1;
                v += bin[k] * w1;
            }
            int hh = tid >> 6;
            float as_ = a1s[tid], ad_ = a1d[tid];
            atomicAdd(&sp[hh], u * as_);
            atomicAdd(&sq[hh], v * as_);
            atomicAdd(&sr[hh], u * ad_);
            atomicAdd(&st[hh], v * ad_);
        }
        __syncthreads();
        if (b == 8) {
            if (tid < 4) { d_p[tid] = sp[tid]; d_q[tid] = sq[tid]; d_r[tid] = sr[tid]; d_t[tid] = st[tid]; }
            for (int idx = tid; idx < 64 * 32; idx += 256) {
                int c = idx >> 5, k = idx & 31;
                d_faW1h[idx] = __floats2half2_rn(faW1[c * 64 + 2 * k], faW1[c * 64 + 2 * k + 1]);
            }
            if (tid < 32) {
                d_fab1h[tid] = __floats2half2_rn(fab1[2 * tid], fab1[2 * tid + 1]);
                d_faW2h[tid] = __floats2half2_rn(faW2[2 * tid], faW2[2 * tid + 1]);
            }
            if (tid < 64) d_fa[tid] = 0.f;
        }
        float pr[4], qt[4];
#pragma unroll
        for (int h = 0; h < 4; h++) { pr[h] = sp[h] + sr[h]; qt[h] = sq[h] + st[h]; }
        int i0 = (b - 8) * 256 + tid;
        int stride = 152 * 256;
        for (int nn = i0; nn < NN; nn += stride) {
            float xn = __ldg(&x[nn]);
            float ex[4];
#pragma unroll
            for (int h = 0; h < 4; h++) {
                float e = xn * pr[h] + qt[h];
                e = (e > 0.f) ? e : 0.2f * e;
                ex[h] = __expf(e);
            }
            d_S0[nn] = make_float4(ex[0], ex[1], ex[2], ex[3]);
            d_S1[nn] = make_float4(ex[0] * xn, ex[1] * xn, ex[2] * xn, ex[3] * xn);
        }
        for (int i = i0; i < BB * 64; i += stride) d_pool[i] = 0.f;
    }
}

// ---------------- GAT-1 edge pass (real edges only): accumulate S0 and S1 ----------------
__global__ void gat1_k(const int* __restrict__ ei, const float* __restrict__ x) {
    int idx = blockIdx.x * 256 + threadIdx.x;
    int s = ei[idx], d = ei[EE + idx];
    float xs = __ldg(&x[s]);
    float xd = __ldg(&x[d]);
    float ex[4];
#pragma unroll
    for (int h = 0; h < 4; h++) {
        float e = xs * d_p[h] + d_q[h] + xd * d_r[h] + d_t[h];
        e = (e > 0.f) ? e : 0.2f * e;
        ex[h] = __expf(e);
    }
    atomicAdd(&d_S0[d], make_float4(ex[0], ex[1], ex[2], ex[3]));
    atomicAdd(&d_S1[d], make_float4(ex[0] * xs, ex[1] * xs, ex[2] * xs, ex[3] * xs));
}

// ---------------- piecewise-linear "GEMM" + GAT-2 self-loop init (half2) ----------------
__global__ void g2_k() {
    __shared__ float thrS[8 * 64];
    int tid = threadIdx.x;  // 256
    for (int i = tid; i < 512; i += 256) thrS[i] = d_thr[i];
    __syncthreads();
    int lane = tid & 31, w = tid >> 5;
    int node = blockIdx.x * 8 + w;
    float4 s0 = d_S0[node], s1 = d_S1[node];
    float wh[4] = { s1.x / s0.x, s1.y / s0.y, s1.z / s0.z, s1.w / s0.w };
    float acc0 = 0.f, acc1 = 0.f, acc2 = 0.f;
#pragma unroll
    for (int hs = 0; hs < 8; hs++) {
        float wv = wh[hs >> 1];
        float t0 = thrS[hs * 64 + lane];
        float t1 = thrS[hs * 64 + 32 + lane];
        bool p0, p1;
        if ((hs & 1) == 0) { p0 = t0 < wv;  p1 = t1 < wv; }
        else               { p0 = t0 <= wv; p1 = t1 <= wv; }
        int cnt = __popc(__ballot_sync(0xffffffffu, p0)) +
                  __popc(__ballot_sync(0xffffffffu, p1));
        const __half2* ptr = &d_tab[(hs * 65 + cnt) * 68];
        uint2 tp = *(const uint2*)&ptr[2 * lane];
        float2 e0 = __half22float2(*(__half2*)&tp.x);
        float2 e1 = __half22float2(*(__half2*)&tp.y);
        acc0 += wv * e0.x + e0.y;
        acc1 += wv * e1.x + e1.y;
        if (lane < 2) {
            float2 e2 = __half22float2(__ldg(&ptr[64 + lane]));
            acc2 += wv * e2.x + e2.y;
        }
    }
    d_gh[node * 32 + lane] = __floats2half2_rn(acc0, acc1);
    if (lane == 0) d_a2s[node] = acc2;
    if (lane == 1) d_a2d[node] = acc2;
    float a2s_n = __shfl_sync(0xffffffffu, acc2, 0);
    float a2d_n = __shfl_sync(0xffffffffu, acc2, 1);
    float el = a2s_n + a2d_n;
    el = (el > 0.f) ? el : 0.2f * el;
    float exs = __expf(el);
    d_out2h[node * 32 + lane] = __floats2half2_rn(exs * acc0, exs * acc1);
    if (lane == 0) d_den2[node] = exs;
}

// ---------------- GAT-2 edge pass: two-phase, fp16 v4.f16x2 REDs (8 lanes/edge) ----------------
__global__ void gat2_k(const int* __restrict__ ei) {
    __shared__ int sS[512];
    __shared__ int sD[512];
    __shared__ float sEx[512];
    int tid = threadIdx.x;
    int e0 = blockIdx.x * 512;
#pragma unroll
    for (int k = 0; k < 2; k++) {
        int i = tid + k * 256;
        int e = e0 + i;
        int s = __ldg(&ei[e]);
        int d = __ldg(&ei[EE + e]);
        float el = __ldg(&d_a2s[s]) + __ldg(&d_a2d[d]);
        el = (el > 0.f) ? el : 0.2f * el;
        float ex = __expf(el);
        sS[i] = s; sD[i] = d; sEx[i] = ex;
        atomicAdd(&d_den2[d], ex);
    }
    __syncthreads();
    int l = tid & 7, grp = tid >> 3;     // 32 groups x 8 lanes
    int base = grp * 16;
#pragma unroll 4
    for (int j = 0; j < 16; j++) {
        int i = base + j;
        int s = sS[i];
        int d = sD[i];
        float ex = sEx[i];
        uint4 gp = *(const uint4*)&d_gh[s * 32 + l * 4];
        float2 a0 = __half22float2(*(__half2*)&gp.x);
        float2 a1 = __half22float2(*(__half2*)&gp.y);
        float2 a2 = __half22float2(*(__half2*)&gp.z);
        float2 a3 = __half22float2(*(__half2*)&gp.w);
        unsigned r0 = pack_h2(ex * a0.x, ex * a0.y);
        unsigned r1 = pack_h2(ex * a1.x, ex * a1.y);
        unsigned r2 = pack_h2(ex * a2.x, ex * a2.y);
        unsigned r3 = pack_h2(ex * a3.x, ex * a3.y);
        asm volatile("red.global.add.noftz.v4.f16x2 [%0], {%1, %2, %3, %4};"
                     :: "l"(&d_out2h[d * 32 + l * 4]),
                        "r"(r0), "r"(r1), "r"(r2), "r"(r3)
                     : "memory");
    }
}

// ---------------- fused: h2 finalize + pooling + feature attention + lean last-block classifier ----------------
__global__ void __launch_bounds__(128) att_k(const float* __restrict__ b2,
                      const float* __restrict__ fab2,
                      const float* __restrict__ clsW, const float* __restrict__ clsb,
                      float* __restrict__ out) {
    __shared__ __align__(16) __half2 W1s[64 * 32];
    __shared__ __half2 b1s[32], w2s[32];
    __shared__ float b2s[64];
    __shared__ float fas[64];
    __shared__ int lastS;
    int tid = threadIdx.x;  // 128
    for (int i = tid; i < 2048; i += 128) W1s[i] = d_faW1h[i];
    if (tid < 32) { b1s[tid] = d_fab1h[tid]; w2s[tid] = d_faW2h[tid]; }
    if (tid < 64) { b2s[tid] = b2[tid]; fas[tid] = 0.f; }
    __syncthreads();
    int n = blockIdx.x * 128 + tid;
    int bg = n >> 6;
    float inv = 1.f / d_den2[n];
    __half2 hh[32];
#pragma unroll
    for (int i = 0; i < 8; i++) {
        uint4 o4 = *(const uint4*)&d_out2h[n * 32 + i * 4];
        float2 f0 = __half22float2(*(__half2*)&o4.x);
        float2 f1 = __half22float2(*(__half2*)&o4.y);
        float2 f2 = __half22float2(*(__half2*)&o4.z);
        float2 f3 = __half22float2(*(__half2*)&o4.w);
        float4 h0, h1;
        h0.x = fmaxf(f0.x * inv + b2s[i * 8 + 0], 0.f);
        h0.y = fmaxf(f0.y * inv + b2s[i * 8 + 1], 0.f);
        h0.z = fmaxf(f1.x * inv + b2s[i * 8 + 2], 0.f);
        h0.w = fmaxf(f1.y * inv + b2s[i * 8 + 3], 0.f);
        h1.x = fmaxf(f2.x * inv + b2s[i * 8 + 4], 0.f);
        h1.y = fmaxf(f2.y * inv + b2s[i * 8 + 5], 0.f);
        h1.z = fmaxf(f3.x * inv + b2s[i * 8 + 6], 0.f);
        h1.w = fmaxf(f3.y * inv + b2s[i * 8 + 7], 0.f);
        atomicAdd((float4*)&d_pool[bg * 64 + i * 8], h0);
        atomicAdd((float4*)&d_pool[bg * 64 + i * 8 + 4], h1);
        hh[i * 4 + 0] = __floats2half2_rn(h0.x, h0.y);
        hh[i * 4 + 1] = __floats2half2_rn(h0.z, h0.w);
        hh[i * 4 + 2] = __floats2half2_rn(h1.x, h1.y);
        hh[i * 4 + 3] = __floats2half2_rn(h1.z, h1.w);
    }
    __half2 acc[32];
#pragma unroll
    for (int i = 0; i < 32; i++) acc[i] = b1s[i];
#pragma unroll
    for (int ci = 0; ci < 32; ci++) {
        __half2 hc0 = __low2half2(hh[ci]);
        __half2 hc1 = __high2half2(hh[ci]);
        const uint4* wr0 = (const uint4*)&W1s[(2 * ci) * 32];
        const uint4* wr1 = (const uint4*)&W1s[(2 * ci + 1) * 32];
#pragma unroll
        for (int i = 0; i < 8; i++) {
            uint4 w0 = wr0[i];
            acc[i * 4 + 0] = __hfma2(hc0, *(__half2*)&w0.x, acc[i * 4 + 0]);
            acc[i * 4 + 1] = __hfma2(hc0, *(__half2*)&w0.y, acc[i * 4 + 1]);
            acc[i * 4 + 2] = __hfma2(hc0, *(__half2*)&w0.z, acc[i * 4 + 2]);
            acc[i * 4 + 3] = __hfma2(hc0, *(__half2*)&w0.w, acc[i * 4 + 3]);
        }
#pragma unroll
        for (int i = 0; i < 8; i++) {
            uint4 w1 = wr1[i];
            acc[i * 4 + 0] = __hfma2(hc1, *(__half2*)&w1.x, acc[i * 4 + 0]);
            acc[i * 4 + 1] = __hfma2(hc1, *(__half2*)&w1.y, acc[i * 4 + 1]);
            acc[i * 4 + 2] = __hfma2(hc1, *(__half2*)&w1.z, acc[i * 4 + 2]);
            acc[i * 4 + 3] = __hfma2(hc1, *(__half2*)&w1.w, acc[i * 4 + 3]);
        }
    }
    __half2 zero2 = __float2half2_rn(0.f);
    __half2 rs = zero2;
#pragma unroll
    for (int i = 0; i < 32; i++)
        rs = __hfma2(__hmax2(acc[i], zero2), w2s[i], rs);
    float res = fab2[0] + __low2float(rs) + __high2float(rs);
    float att = 1.f / (1.f + __expf(-res));
    atomicAdd(&fas[n & 63], att);
    __syncthreads();
    if (tid < 64) atomicAdd(&d_fa[tid], fas[tid]);
    __syncthreads();
    if (tid == 0) {
        __threadfence();                       // release: block's REDs visible before ctr
        lastS = atomicAdd(&d_ctr, 1);
    }
    __syncthreads();
    if (lastS == (int)gridDim.x - 1) {
        __threadfence();                       // acquire
        const float pinv = 1.f / (float)FEATN;
        for (int g = tid; g < BB; g += 128) {
            float o0 = clsb[0], o1 = clsb[1], o2 = clsb[2], o3 = clsb[3], o4 = clsb[4];
            const float* pr = &d_pool[g * 64];
#pragma unroll 8
            for (int c = 0; c < 64; c++) {
                float pv = pr[c] * pinv;
                o0 += pv * clsW[c * NCLS + 0];
                o1 += pv * clsW[c * NCLS + 1];
                o2 += pv * clsW[c * NCLS + 2];
                o3 += pv * clsW[c * NCLS + 3];
                o4 += pv * clsW[c * NCLS + 4];
            }
            out[g * NCLS + 0] = o0;
            out[g * NCLS + 1] = o1;
            out[g * NCLS + 2] = o2;
            out[g * NCLS + 3] = o3;
            out[g * NCLS + 4] = o4;
        }
        if (tid < 64) out[BB * NCLS + tid] = d_fa[tid] * (1.f / (float)BB);
        __syncthreads();
        if (tid == 0) d_ctr = 0;               // self-reset for next call / replay
    }
}

extern "C" void kernel_launch(void* const* d_in, const int* in_sizes, int n_in,
                              void* d_out, int out_size) {
    const float* x    = (const float*)d_in[0];
    const int*   ei   = (const int*)d_in[1];
    const float* Win  = (const float*)d_in[3];
    const float* bin  = (const float*)d_in[4];
    const float* W1   = (const float*)d_in[5];
    const float* a1s  = (const float*)d_in[6];
    const float* a1d  = (const float*)d_in[7];
    const float* b1   = (const float*)d_in[8];
    const float* W2   = (const float*)d_in[9];
    const float* a2s  = (const float*)d_in[10];
    const float* a2d  = (const float*)d_in[11];
    const float* b2   = (const float*)d_in[12];
    const float* faW1 = (const float*)d_in[13];
    const float* fab1 = (const float*)d_in[14];
    const float* faW2 = (const float*)d_in[15];
    const float* fab2 = (const float*)d_in[16];
    const float* clsW = (const float*)d_in[17];
    const float* clsb = (const float*)d_in[18];
    float* out = (float*)d_out;

    init_k<<<160, 256>>>(x, Win, bin, W1, a1s, a1d, b1, W2, a2s, a2d, faW1, fab1, faW2);
    gat1_k<<<EE / 256, 256>>>(ei, x);
    g2_k<<<NN / 8, 256>>>();
    gat2_k<<<EE / 512, 256>>>(ei);
    att_k<<<NN / 128, 128>>>(b2, fab2, clsW, clsb, out);
}

// round 16
// speedup vs baseline: 1.0794x; 1.0159x over previous
#include <cuda_runtime.h>
#include <cuda_fp16.h>

#define NN 65536
#define EE 524288
#define BB 1024
#define FEATN 64
#define NCLS 5
#define INF_F __int_as_float(0x7f800000)

// ---------------- scratch (device globals; no allocs allowed) ----------------
__device__ float d_p[4], d_q[4], d_r[4], d_t[4];
__device__ __align__(16) float4 d_S0[NN];
__device__ __align__(16) float4 d_S1[NN];
__device__ __align__(16) __half2 d_gh[NN * 32];      // g rows, fp16
__device__ float d_a2s[NN];
__device__ float d_a2d[NN];
__device__ float d_den2[NN];
__device__ __align__(16) __half2 d_out2h[NN * 32];   // gat2 numerator, fp16 (init in g2_k)
__device__ __align__(16) float d_pool[BB * 64];
__device__ float d_fa[64];
__device__ int d_ctr;                                 // zero-init; self-resets each call
// piecewise-linear GEMM tables (half precision)
__device__ float d_thr[8 * 64];
__device__ __align__(16) __half2 d_tab[8 * 65 * 68];
// feature-attention weights, half2-packed
__device__ __align__(16) __half2 d_faW1h[64 * 32];
__device__ __align__(8)  __half2 d_fab1h[32];
__device__ __align__(8)  __half2 d_faW2h[32];

__device__ __forceinline__ unsigned pack_h2(float a, float b) {
    __half2 h = __floats2half2_rn(a, b);
    return *(unsigned*)&h;
}

// ---------------- fused init: tables + self-loop S0/S1 + zeroing + weight packing ----------------
__global__ void init_k(const float* __restrict__ x,
                       const float* __restrict__ Win, const float* __restrict__ bin,
                       const float* __restrict__ W1, const float* __restrict__ a1s,
                       const float* __restrict__ a1d, const float* __restrict__ b1,
                       const float* __restrict__ W2, const float* __restrict__ a2sv,
                       const float* __restrict__ a2dv, const float* __restrict__ faW1,
                       const float* __restrict__ fab1, const float* __restrict__ faW2) {
    int b = blockIdx.x;
    int tid = threadIdx.x;      // 256
    if (b < 8) {
        int hs = b, h = hs >> 1, set = hs & 1;
        __shared__ float W2s[64 * 68];
        __shared__ float us[64], vbs[64], key[64];
        __shared__ int sidx[64];
        __shared__ unsigned char memb[64];
        __shared__ int n_s;
        if (tid < 64) {
            float u = 0.f, v = 0.f;
            for (int k = 0; k < 64; k++) {
                float w1 = W1[k * 256 + h * 64 + tid];
                u += Win[k] * w1;
                v += bin[k] * w1;
            }
            float vb = v + b1[h * 64 + tid];
            us[tid] = u; vbs[tid] = vb;
            bool m = (set == 0) ? (u > 0.f) : (u < 0.f);
            memb[tid] = m ? 1 : 0;
            key[tid] = m ? (-vb / u) : INF_F;
        }
        for (int i = tid; i < 64 * 64; i += 256) {
            int j = i >> 6, c = i & 63;
            W2s[j * 68 + c] = W2[(h * 64 + j) * 64 + c];
        }
        __syncthreads();
        if (tid < 64) {
            float as = 0.f, ad = 0.f;
            for (int c = 0; c < 64; c++) {
                float w2 = W2s[tid * 68 + c];
                as += w2 * a2sv[c];
                ad += w2 * a2dv[c];
            }
            W2s[tid * 68 + 64] = as;
            W2s[tid * 68 + 65] = ad;
            W2s[tid * 68 + 66] = 0.f;
            W2s[tid * 68 + 67] = 0.f;
        }
        __syncthreads();
        if (tid < 64) {
            float ki = key[tid];
            int r = 0;
            for (int j = 0; j < 64; j++) {
                float kj = key[j];
                r += (kj < ki) || (kj == ki && j < tid);
            }
            sidx[r] = tid;
        }
        if (tid == 0) {
            int n = 0;
            for (int j = 0; j < 64; j++) n += memb[j];
            n_s = n;
        }
        __syncthreads();
        int n = n_s;
        if (tid < 64) d_thr[hs * 64 + tid] = key[sidx[tid]];
        if (tid < 68) {
            int c = tid;
            if (set == 0) {
                float base = 0.f;
                for (int j = 0; j < 64; j++)
                    if (us[j] == 0.f && vbs[j] > 0.f) base += vbs[j] * W2s[j * 68 + c];
                float au = 0.f, av = base;
                d_tab[(hs * 65 + 0) * 68 + c] = __float22half2_rn(make_float2(au, av));
                for (int s = 0; s < 64; s++) {
                    if (s < n) {
                        int k = sidx[s];
                        au += us[k] * W2s[k * 68 + c];
                        av += vbs[k] * W2s[k * 68 + c];
                    }
                    d_tab[(hs * 65 + s + 1) * 68 + c] = __float22half2_rn(make_float2(au, av));
                }
            } else {
                for (int s = n; s <= 64; s++)
                    d_tab[(hs * 65 + s) * 68 + c] = __float22half2_rn(make_float2(0.f, 0.f));
                float au = 0.f, av = 0.f;
                for (int s = n - 1; s >= 0; s--) {
                    int k = sidx[s];
                    au += us[k] * W2s[k * 68 + c];
                    av += vbs[k] * W2s[k * 68 + c];
                    d_tab[(hs * 65 + s) * 68 + c] = __float22half2_rn(make_float2(au, av));
                }
            }
        }
    } else {
        __shared__ float sp[4], sq[4], sr[4], st[4];
        if (tid < 4) { sp[tid] = 0.f; sq[tid] = 0.f; sr[tid] = 0.f; st[tid] = 0.f; }
        __syncthreads();
        {
            float u = 0.f, v = 0.f;
            for (int k = 0; k < 64; k++) {
                float w1 = W1[k * 256 + tid];
                u += Win[k] * w1;
                v += bin[k] * w1;
            }
            int hh = tid >> 6;
            float as_ = a1s[tid], ad_ = a1d[tid];
            atomicAdd(&sp[hh], u * as_);
            atomicAdd(&sq[hh], v * as_);
            atomicAdd(&sr[hh], u * ad_);
            atomicAdd(&st[hh], v * ad_);
        }
        __syncthreads();
        if (b == 8) {
            if (tid < 4) { d_p[tid] = sp[tid]; d_q[tid] = sq[tid]; d_r[tid] = sr[tid]; d_t[tid] = st[tid]; }
            for (int idx = tid; idx < 64 * 32; idx += 256) {
                int c = idx >> 5, k = idx & 31;
                d_faW1h[idx] = __floats2half2_rn(faW1[c * 64 + 2 * k], faW1[c * 64 + 2 * k + 1]);
            }
            if (tid < 32) {
                d_fab1h[tid] = __floats2half2_rn(fab1[2 * tid], fab1[2 * tid + 1]);
                d_faW2h[tid] = __floats2half2_rn(faW2[2 * tid], faW2[2 * tid + 1]);
            }
            if (tid < 64) d_fa[tid] = 0.f;
        }
        float pr[4], qt[4];
#pragma unroll
        for (int h = 0; h < 4; h++) { pr[h] = sp[h] + sr[h]; qt[h] = sq[h] + st[h]; }
        int i0 = (b - 8) * 256 + tid;
        int stride = 152 * 256;
        for (int nn = i0; nn < NN; nn += stride) {
            float xn = __ldg(&x[nn]);
            float ex[4];
#pragma unroll
            for (int h = 0; h < 4; h++) {
                float e = xn * pr[h] + qt[h];
                e = (e > 0.f) ? e : 0.2f * e;
                ex[h] = __expf(e);
            }
            d_S0[nn] = make_float4(ex[0], ex[1], ex[2], ex[3]);
            d_S1[nn] = make_float4(ex[0] * xn, ex[1] * xn, ex[2] * xn, ex[3] * xn);
        }
        for (int i = i0; i < BB * 64; i += stride) d_pool[i] = 0.f;
    }
}

// ---------------- GAT-1 edge pass (real edges only): accumulate S0 and S1 ----------------
__global__ void gat1_k(const int* __restrict__ ei, const float* __restrict__ x) {
    int idx = blockIdx.x * 256 + threadIdx.x;
    int s = ei[idx], d = ei[EE + idx];
    float xs = __ldg(&x[s]);
    float xd = __ldg(&x[d]);
    float ex[4];
#pragma unroll
    for (int h = 0; h < 4; h++) {
        float e = xs * d_p[h] + d_q[h] + xd * d_r[h] + d_t[h];
        e = (e > 0.f) ? e : 0.2f * e;
        ex[h] = __expf(e);
    }
    atomicAdd(&d_S0[d], make_float4(ex[0], ex[1], ex[2], ex[3]));
    atomicAdd(&d_S1[d], make_float4(ex[0] * xs, ex[1] * xs, ex[2] * xs, ex[3] * xs));
}

// ---------------- piecewise-linear "GEMM" + GAT-2 self-loop init (half2) ----------------
__global__ void g2_k() {
    __shared__ float thrS[8 * 64];
    int tid = threadIdx.x;  // 256
    for (int i = tid; i < 512; i += 256) thrS[i] = d_thr[i];
    __syncthreads();
    int lane = tid & 31, w = tid >> 5;
    int node = blockIdx.x * 8 + w;
    float4 s0 = d_S0[node], s1 = d_S1[node];
    float wh[4] = { s1.x / s0.x, s1.y / s0.y, s1.z / s0.z, s1.w / s0.w };
    float acc0 = 0.f, acc1 = 0.f, acc2 = 0.f;
#pragma unroll
    for (int hs = 0; hs < 8; hs++) {
        float wv = wh[hs >> 1];
        float t0 = thrS[hs * 64 + lane];
        float t1 = thrS[hs * 64 + 32 + lane];
        bool p0, p1;
        if ((hs & 1) == 0) { p0 = t0 < wv;  p1 = t1 < wv; }
        else               { p0 = t0 <= wv; p1 = t1 <= wv; }
        int cnt = __popc(__ballot_sync(0xffffffffu, p0)) +
                  __popc(__ballot_sync(0xffffffffu, p1));
        const __half2* ptr = &d_tab[(hs * 65 + cnt) * 68];
        uint2 tp = *(const uint2*)&ptr[2 * lane];
        float2 e0 = __half22float2(*(__half2*)&tp.x);
        float2 e1 = __half22float2(*(__half2*)&tp.y);
        acc0 += wv * e0.x + e0.y;
        acc1 += wv * e1.x + e1.y;
        if (lane < 2) {
            float2 e2 = __half22float2(__ldg(&ptr[64 + lane]));
            acc2 += wv * e2.x + e2.y;
        }
    }
    d_gh[node * 32 + lane] = __floats2half2_rn(acc0, acc1);
    if (lane == 0) d_a2s[node] = acc2;
    if (lane == 1) d_a2d[node] = acc2;
    float a2s_n = __shfl_sync(0xffffffffu, acc2, 0);
    float a2d_n = __shfl_sync(0xffffffffu, acc2, 1);
    float el = a2s_n + a2d_n;
    el = (el > 0.f) ? el : 0.2f * el;
    float exs = __expf(el);
    d_out2h[node * 32 + lane] = __floats2half2_rn(exs * acc0, exs * acc1);
    if (lane == 0) d_den2[node] = exs;
}

// ---------------- GAT-2 edge pass: two-phase, fp16 v4.f16x2 REDs (8 lanes/edge) ----------------
__global__ void gat2_k(const int* __restrict__ ei) {
    __shared__ int sS[512];
    __shared__ int sD[512];
    __shared__ float sEx[512];
    int tid = threadIdx.x;
    int e0 = blockIdx.x * 512;
#pragma unroll
    for (int k = 0; k < 2; k++) {
        int i = tid + k * 256;
        int e = e0 + i;
        int s = __ldg(&ei[e]);
        int d = __ldg(&ei[EE + e]);
        float el = __ldg(&d_a2s[s]) + __ldg(&d_a2d[d]);
        el = (el > 0.f) ? el : 0.2f * el;
        float ex = __expf(el);
        sS[i] = s; sD[i] = d; sEx[i] = ex;
        atomicAdd(&d_den2[d], ex);
    }
    __syncthreads();
    int l = tid & 7, grp = tid >> 3;     // 32 groups x 8 lanes
    int base = grp * 16;
#pragma unroll 4
    for (int j = 0; j < 16; j++) {
        int i = base + j;
        int s = sS[i];
        int d = sD[i];
        float ex = sEx[i];
        uint4 gp = *(const uint4*)&d_gh[s * 32 + l * 4];
        float2 a0 = __half22float2(*(__half2*)&gp.x);
        float2 a1 = __half22float2(*(__half2*)&gp.y);
        float2 a2 = __half22float2(*(__half2*)&gp.z);
        float2 a3 = __half22float2(*(__half2*)&gp.w);
        unsigned r0 = pack_h2(ex * a0.x, ex * a0.y);
        unsigned r1 = pack_h2(ex * a1.x, ex * a1.y);
        unsigned r2 = pack_h2(ex * a2.x, ex * a2.y);
        unsigned r3 = pack_h2(ex * a3.x, ex * a3.y);
        asm volatile("red.global.add.noftz.v4.f16x2 [%0], {%1, %2, %3, %4};"
                     :: "l"(&d_out2h[d * 32 + l * 4]),
                        "r"(r0), "r"(r1), "r"(r2), "r"(r3)
                     : "memory");
    }
}

// ---------------- fused: h2 finalize + pooling + feature attention + lean last-block classifier ----------------
__global__ void __launch_bounds__(128) att_k(const float* __restrict__ b2,
                      const float* __restrict__ fab2,
                      const float* __restrict__ clsW, const float* __restrict__ clsb,
                      float* __restrict__ out) {
    __shared__ __align__(16) __half2 W1s[64 * 32];
    __shared__ __half2 b1s[32], w2s[32];
    __shared__ float b2s[64];
    __shared__ float fas[64];
    __shared__ int lastS;
    int tid = threadIdx.x;  // 128
    for (int i = tid; i < 2048; i += 128) W1s[i] = d_faW1h[i];
    if (tid < 32) { b1s[tid] = d_fab1h[tid]; w2s[tid] = d_faW2h[tid]; }
    if (tid < 64) { b2s[tid] = b2[tid]; fas[tid] = 0.f; }
    __syncthreads();
    int n = blockIdx.x * 128 + tid;
    int bg = n >> 6;
    float inv = 1.f / d_den2[n];
    __half2 hh[32];
#pragma unroll
    for (int i = 0; i < 8; i++) {
        uint4 o4 = *(const uint4*)&d_out2h[n * 32 + i * 4];
        float2 f0 = __half22float2(*(__half2*)&o4.x);
        float2 f1 = __half22float2(*(__half2*)&o4.y);
        float2 f2 = __half22float2(*(__half2*)&o4.z);
        float2 f3 = __half22float2(*(__half2*)&o4.w);
        float4 h0, h1;
        h0.x = fmaxf(f0.x * inv + b2s[i * 8 + 0], 0.f);
        h0.y = fmaxf(f0.y * inv + b2s[i * 8 + 1], 0.f);
        h0.z = fmaxf(f1.x * inv + b2s[i * 8 + 2], 0.f);
        h0.w = fmaxf(f1.y * inv + b2s[i * 8 + 3], 0.f);
        h1.x = fmaxf(f2.x * inv + b2s[i * 8 + 4], 0.f);
        h1.y = fmaxf(f2.y * inv + b2s[i * 8 + 5], 0.f);
        h1.z = fmaxf(f3.x * inv + b2s[i * 8 + 6], 0.f);
        h1.w = fmaxf(f3.y * inv + b2s[i * 8 + 7], 0.f);
        atomicAdd((float4*)&d_pool[bg * 64 + i * 8], h0);
        atomicAdd((float4*)&d_pool[bg * 64 + i * 8 + 4], h1);
        hh[i * 4 + 0] = __floats2half2_rn(h0.x, h0.y);
        hh[i * 4 + 1] = __floats2half2_rn(h0.z, h0.w);
        hh[i * 4 + 2] = __floats2half2_rn(h1.x, h1.y);
        hh[i * 4 + 3] = __floats2half2_rn(h1.z, h1.w);
    }
    __half2 acc[32];
#pragma unroll
    for (int i = 0; i < 32; i++) acc[i] = b1s[i];
#pragma unroll
    for (int ci = 0; ci < 32; ci++) {
        __half2 hc0 = __low2half2(hh[ci]);
        __half2 hc1 = __high2half2(hh[ci]);
        const uint4* wr0 = (const uint4*)&W1s[(2 * ci) * 32];
        const uint4* wr1 = (const uint4*)&W1s[(2 * ci + 1) * 32];
#pragma unroll
        for (int i = 0; i < 8; i++) {
            uint4 w0 = wr0[i];
            acc[i * 4 + 0] = __hfma2(hc0, *(__half2*)&w0.x, acc[i * 4 + 0]);
            acc[i * 4 + 1] = __hfma2(hc0, *(__half2*)&w0.y, acc[i * 4 + 1]);
            acc[i * 4 + 2] = __hfma2(hc0, *(__half2*)&w0.z, acc[i * 4 + 2]);
            acc[i * 4 + 3] = __hfma2(hc0, *(__half2*)&w0.w, acc[i * 4 + 3]);
        }
#pragma unroll
        for (int i = 0; i < 8; i++) {
            uint4 w1 = wr1[i];
            acc[i * 4 + 0] = __hfma2(hc1, *(__half2*)&w1.x, acc[i * 4 + 0]);
            acc[i * 4 + 1] = __hfma2(hc1, *(__half2*)&w1.y, acc[i * 4 + 1]);
            acc[i * 4 + 2] = __hfma2(hc1, *(__half2*)&w1.z, acc[i * 4 + 2]);
            acc[i * 4 + 3] = __hfma2(hc1, *(__half2*)&w1.w, acc[i * 4 + 3]);
        }
    }
    __half2 zero2 = __float2half2_rn(0.f);
    __half2 rs = zero2;
#pragma unroll
    for (int i = 0; i < 32; i++)
        rs = __hfma2(__hmax2(acc[i], zero2), w2s[i], rs);
    float res = fab2[0] + __low2float(rs) + __high2float(rs);
    float att = 1.f / (1.f + __expf(-res));
    atomicAdd(&fas[n & 63], att);
    __syncthreads();
    if (tid < 64) atomicAdd(&d_fa[tid], fas[tid]);
    __syncthreads();
    if (tid == 0) {
        __threadfence();                       // release: block's REDs visible before ctr
        lastS = atomicAdd(&d_ctr, 1);
    }
    __syncthreads();
    if (lastS == (int)gridDim.x - 1) {
        __threadfence();                       // acquire
        const float pinv = 1.f / (float)FEATN;
        for (int g = tid; g < BB; g += 128) {
            float o0 = clsb[0], o1 = clsb[1], o2 = clsb[2], o3 = clsb[3], o4 = clsb[4];
            const float* pr = &d_pool[g * 64];
#pragma unroll 8
            for (int c = 0; c < 64; c++) {
                float pv = pr[c] * pinv;
                o0 += pv * clsW[c * NCLS + 0];
                o1 += pv * clsW[c * NCLS + 1];
                o2 += pv * clsW[c * NCLS + 2];
                o3 += pv * clsW[c * NCLS + 3];
                o4 += pv * clsW[c * NCLS + 4];
            }
            out[g * NCLS + 0] = o0;
            out[g * NCLS + 1] = o1;
            out[g * NCLS + 2] = o2;
            out[g * NCLS + 3] = o3;
            out[g * NCLS + 4] = o4;
        }
        if (tid < 64) out[BB * NCLS + tid] = d_fa[tid] * (1.f / (float)BB);
        __syncthreads();
        if (tid == 0) d_ctr = 0;               // self-reset for next call / replay
    }
}

extern "C" void kernel_launch(void* const* d_in, const int* in_sizes, int n_in,
                              void* d_out, int out_size) {
    const float* x    = (const float*)d_in[0];
    const int*   ei   = (const int*)d_in[1];
    const float* Win  = (const float*)d_in[3];
    const float* bin  = (const float*)d_in[4];
    const float* W1   = (const float*)d_in[5];
    const float* a1s  = (const float*)d_in[6];
    const float* a1d  = (const float*)d_in[7];
    const float* b1   = (const float*)d_in[8];
    const float* W2   = (const float*)d_in[9];
    const float* a2s  = (const float*)d_in[10];
    const float* a2d  = (const float*)d_in[11];
    const float* b2   = (const float*)d_in[12];
    const float* faW1 = (const float*)d_in[13];
    const float* fab1 = (const float*)d_in[14];
    const float* faW2 = (const float*)d_in[15];
    const float* fab2 = (const float*)d_in[16];
    const float* clsW = (const float*)d_in[17];
    const float* clsb = (const float*)d_in[18];
    float* out = (float*)d_out;

    init_k<<<160, 256>>>(x, Win, bin, W1, a1s, a1d, b1, W2, a2s, a2d, faW1, fab1, faW2);
    gat1_k<<<EE / 256, 256>>>(ei, x);
    g2_k<<<NN / 8, 256>>>();
    gat2_k<<<EE / 512, 256>>>(ei);
    att_k<<<NN / 128, 128>>>(b2, fab2, clsW, clsb, out);
}

// round 17
// speedup vs baseline: 1.3596x; 1.2596x over previous
#include <cuda_runtime.h>
#include <cuda_fp16.h>

#define NN 65536
#define EE 524288
#define BB 1024
#define FEATN 64
#define NCLS 5
#define INF_F __int_as_float(0x7f800000)

// ---------------- scratch (device globals; no allocs allowed) ----------------
__device__ float d_p[4], d_q[4], d_r[4], d_t[4];
__device__ __align__(16) float4 d_S0[NN];
__device__ __align__(16) float4 d_S1[NN];
__device__ __align__(16) __half2 d_gh[NN * 32];      // g rows, fp16
__device__ float d_a2s[NN];
__device__ float d_a2d[NN];
__device__ float d_den2[NN];
__device__ __align__(16) __half2 d_out2h[NN * 32];   // gat2 numerator, fp16 (init in g2_k)
__device__ __align__(16) float d_pool[BB * 64];      // written by STG in att_k (no zero needed)
__device__ float d_fa[64];
// piecewise-linear GEMM tables (half precision)
__device__ float d_thr[8 * 64];
__device__ __align__(16) __half2 d_tab[8 * 65 * 68];
// feature-attention weights, half2-packed
__device__ __align__(16) __half2 d_faW1h[64 * 32];
__device__ __align__(8)  __half2 d_fab1h[32];
__device__ __align__(8)  __half2 d_faW2h[32];

__device__ __forceinline__ unsigned pack_h2(float a, float b) {
    __half2 h = __floats2half2_rn(a, b);
    return *(unsigned*)&h;
}

// ---------------- fused init: tables + self-loop S0/S1 + weight packing ----------------
__global__ void init_k(const float* __restrict__ x,
                       const float* __restrict__ Win, const float* __restrict__ bin,
                       const float* __restrict__ W1, const float* __restrict__ a1s,
                       const float* __restrict__ a1d, const float* __restrict__ b1,
                       const float* __restrict__ W2, const float* __restrict__ a2sv,
                       const float* __restrict__ a2dv, const float* __restrict__ faW1,
                       const float* __restrict__ fab1, const float* __restrict__ faW2) {
    int b = blockIdx.x;
    int tid = threadIdx.x;      // 256
    if (b < 8) {
        int hs = b, h = hs >> 1, set = hs & 1;
        __shared__ float W2s[64 * 68];
        __shared__ float us[64], vbs[64], key[64];
        __shared__ int sidx[64];
        __shared__ unsigned char memb[64];
        __shared__ int n_s;
        if (tid < 64) {
            float u = 0.f, v = 0.f;
            for (int k = 0; k < 64; k++) {
                float w1 = W1[k * 256 + h * 64 + tid];
                u += Win[k] * w1;
                v += bin[k] * w1;
            }
            float vb = v + b1[h * 64 + tid];
            us[tid] = u; vbs[tid] = vb;
            bool m = (set == 0) ? (u > 0.f) : (u < 0.f);
            memb[tid] = m ? 1 : 0;
            key[tid] = m ? (-vb / u) : INF_F;
        }
        for (int i = tid; i < 64 * 64; i += 256) {
            int j = i >> 6, c = i & 63;
            W2s[j * 68 + c] = W2[(h * 64 + j) * 64 + c];
        }
        __syncthreads();
        if (tid < 64) {
            float as = 0.f, ad = 0.f;
            for (int c = 0; c < 64; c++) {
                float w2 = W2s[tid * 68 + c];
                as += w2 * a2sv[c];
                ad += w2 * a2dv[c];
            }
            W2s[tid * 68 + 64] = as;
            W2s[tid * 68 + 65] = ad;
            W2s[tid * 68 + 66] = 0.f;
            W2s[tid * 68 + 67] = 0.f;
        }
        __syncthreads();
        if (tid < 64) {
            float ki = key[tid];
            int r = 0;
            for (int j = 0; j < 64; j++) {
                float kj = key[j];
                r += (kj < ki) || (kj == ki && j < tid);
            }
            sidx[r] = tid;
        }
        if (tid == 0) {
            int n = 0;
            for (int j = 0; j < 64; j++) n += memb[j];
            n_s = n;
        }
        __syncthreads();
        int n = n_s;
        if (tid < 64) d_thr[hs * 64 + tid] = key[sidx[tid]];
        if (tid < 68) {
            int c = tid;
            if (set == 0) {
                float base = 0.f;
                for (int j = 0; j < 64; j++)
                    if (us[j] == 0.f && vbs[j] > 0.f) base += vbs[j] * W2s[j * 68 + c];
                float au = 0.f, av = base;
                d_tab[(hs * 65 + 0) * 68 + c] = __float22half2_rn(make_float2(au, av));
                for (int s = 0; s < 64; s++) {
                    if (s < n) {
                        int k = sidx[s];
                        au += us[k] * W2s[k * 68 + c];
                        av += vbs[k] * W2s[k * 68 + c];
                    }
                    d_tab[(hs * 65 + s + 1) * 68 + c] = __float22half2_rn(make_float2(au, av));
                }
            } else {
                for (int s = n; s <= 64; s++)
                    d_tab[(hs * 65 + s) * 68 + c] = __float22half2_rn(make_float2(0.f, 0.f));
                float au = 0.f, av = 0.f;
                for (int s = n - 1; s >= 0; s--) {
                    int k = sidx[s];
                    au += us[k] * W2s[k * 68 + c];
                    av += vbs[k] * W2s[k * 68 + c];
                    d_tab[(hs * 65 + s) * 68 + c] = __float22half2_rn(make_float2(au, av));
                }
            }
        }
    } else {
        __shared__ float sp[4], sq[4], sr[4], st[4];
        if (tid < 4) { sp[tid] = 0.f; sq[tid] = 0.f; sr[tid] = 0.f; st[tid] = 0.f; }
        __syncthreads();
        {
            float u = 0.f, v = 0.f;
            for (int k = 0; k < 64; k++) {
                float w1 = W1[k * 256 + tid];
                u += Win[k] * w1;
                v += bin[k] * w1;
            }
            int hh = tid >> 6;
            float as_ = a1s[tid], ad_ = a1d[tid];
            atomicAdd(&sp[hh], u * as_);
            atomicAdd(&sq[hh], v * as_);
            atomicAdd(&sr[hh], u * ad_);
            atomicAdd(&st[hh], v * ad_);
        }
        __syncthreads();
        if (b == 8) {
            if (tid < 4) { d_p[tid] = sp[tid]; d_q[tid] = sq[tid]; d_r[tid] = sr[tid]; d_t[tid] = st[tid]; }
            for (int idx = tid; idx < 64 * 32; idx += 256) {
                int c = idx >> 5, k = idx & 31;
                d_faW1h[idx] = __floats2half2_rn(faW1[c * 64 + 2 * k], faW1[c * 64 + 2 * k + 1]);
            }
            if (tid < 32) {
                d_fab1h[tid] = __floats2half2_rn(fab1[2 * tid], fab1[2 * tid + 1]);
                d_faW2h[tid] = __floats2half2_rn(faW2[2 * tid], faW2[2 * tid + 1]);
            }
            if (tid < 64) d_fa[tid] = 0.f;
        }
        float pr[4], qt[4];
#pragma unroll
        for (int h = 0; h < 4; h++) { pr[h] = sp[h] + sr[h]; qt[h] = sq[h] + st[h]; }
        int i0 = (b - 8) * 256 + tid;
        int stride = 152 * 256;
        for (int nn = i0; nn < NN; nn += stride) {
            float xn = __ldg(&x[nn]);
            float ex[4];
#pragma unroll
            for (int h = 0; h < 4; h++) {
                float e = xn * pr[h] + qt[h];
                e = (e > 0.f) ? e : 0.2f * e;
                ex[h] = __expf(e);
            }
            d_S0[nn] = make_float4(ex[0], ex[1], ex[2], ex[3]);
            d_S1[nn] = make_float4(ex[0] * xn, ex[1] * xn, ex[2] * xn, ex[3] * xn);
        }
    }
}

// ---------------- GAT-1 edge pass (real edges only): accumulate S0 and S1 ----------------
__global__ void gat1_k(const int* __restrict__ ei, const float* __restrict__ x) {
    int idx = blockIdx.x * 256 + threadIdx.x;
    int s = ei[idx], d = ei[EE + idx];
    float xs = __ldg(&x[s]);
    float xd = __ldg(&x[d]);
    float ex[4];
#pragma unroll
    for (int h = 0; h < 4; h++) {
        float e = xs * d_p[h] + d_q[h] + xd * d_r[h] + d_t[h];
        e = (e > 0.f) ? e : 0.2f * e;
        ex[h] = __expf(e);
    }
    atomicAdd(&d_S0[d], make_float4(ex[0], ex[1], ex[2], ex[3]));
    atomicAdd(&d_S1[d], make_float4(ex[0] * xs, ex[1] * xs, ex[2] * xs, ex[3] * xs));
}

// ---------------- piecewise-linear "GEMM" + GAT-2 self-loop init (half2) ----------------
__global__ void g2_k() {
    __shared__ float thrS[8 * 64];
    int tid = threadIdx.x;  // 256
    for (int i = tid; i < 512; i += 256) thrS[i] = d_thr[i];
    __syncthreads();
    int lane = tid & 31, w = tid >> 5;
    int node = blockIdx.x * 8 + w;
    float4 s0 = d_S0[node], s1 = d_S1[node];
    float wh[4] = { s1.x / s0.x, s1.y / s0.y, s1.z / s0.z, s1.w / s0.w };
    float acc0 = 0.f, acc1 = 0.f, acc2 = 0.f;
#pragma unroll
    for (int hs = 0; hs < 8; hs++) {
        float wv = wh[hs >> 1];
        float t0 = thrS[hs * 64 + lane];
        float t1 = thrS[hs * 64 + 32 + lane];
        bool p0, p1;
        if ((hs & 1) == 0) { p0 = t0 < wv;  p1 = t1 < wv; }
        else               { p0 = t0 <= wv; p1 = t1 <= wv; }
        int cnt = __popc(__ballot_sync(0xffffffffu, p0)) +
                  __popc(__ballot_sync(0xffffffffu, p1));
        const __half2* ptr = &d_tab[(hs * 65 + cnt) * 68];
        uint2 tp = *(const uint2*)&ptr[2 * lane];
        float2 e0 = __half22float2(*(__half2*)&tp.x);
        float2 e1 = __half22float2(*(__half2*)&tp.y);
        acc0 += wv * e0.x + e0.y;
        acc1 += wv * e1.x + e1.y;
        if (lane < 2) {
            float2 e2 = __half22float2(__ldg(&ptr[64 + lane]));
            acc2 += wv * e2.x + e2.y;
        }
    }
    d_gh[node * 32 + lane] = __floats2half2_rn(acc0, acc1);
    if (lane == 0) d_a2s[node] = acc2;
    if (lane == 1) d_a2d[node] = acc2;
    float a2s_n = __shfl_sync(0xffffffffu, acc2, 0);
    float a2d_n = __shfl_sync(0xffffffffu, acc2, 1);
    float el = a2s_n + a2d_n;
    el = (el > 0.f) ? el : 0.2f * el;
    float exs = __expf(el);
    d_out2h[node * 32 + lane] = __floats2half2_rn(exs * acc0, exs * acc1);
    if (lane == 0) d_den2[node] = exs;
}

// ---------------- GAT-2 edge pass: two-phase, fp16 v4.f16x2 REDs (8 lanes/edge) ----------------
__global__ void gat2_k(const int* __restrict__ ei) {
    __shared__ int sS[512];
    __shared__ int sD[512];
    __shared__ float sEx[512];
    int tid = threadIdx.x;
    int e0 = blockIdx.x * 512;
#pragma unroll
    for (int k = 0; k < 2; k++) {
        int i = tid + k * 256;
        int e = e0 + i;
        int s = __ldg(&ei[e]);
        int d = __ldg(&ei[EE + e]);
        float el = __ldg(&d_a2s[s]) + __ldg(&d_a2d[d]);
        el = (el > 0.f) ? el : 0.2f * el;
        float ex = __expf(el);
        sS[i] = s; sD[i] = d; sEx[i] = ex;
        atomicAdd(&d_den2[d], ex);
    }
    __syncthreads();
    int l = tid & 7, grp = tid >> 3;     // 32 groups x 8 lanes
    int base = grp * 16;
#pragma unroll 4
    for (int j = 0; j < 16; j++) {
        int i = base + j;
        int s = sS[i];
        int d = sD[i];
        float ex = sEx[i];
        uint4 gp = *(const uint4*)&d_gh[s * 32 + l * 4];
        float2 a0 = __half22float2(*(__half2*)&gp.x);
        float2 a1 = __half22float2(*(__half2*)&gp.y);
        float2 a2 = __half22float2(*(__half2*)&gp.z);
        float2 a3 = __half22float2(*(__half2*)&gp.w);
        unsigned r0 = pack_h2(ex * a0.x, ex * a0.y);
        unsigned r1 = pack_h2(ex * a1.x, ex * a1.y);
        unsigned r2 = pack_h2(ex * a2.x, ex * a2.y);
        unsigned r3 = pack_h2(ex * a3.x, ex * a3.y);
        asm volatile("red.global.add.noftz.v4.f16x2 [%0], {%1, %2, %3, %4};"
                     :: "l"(&d_out2h[d * 32 + l * 4]),
                        "r"(r0), "r"(r1), "r"(r2), "r"(r3)
                     : "memory");
    }
}

// ---------------- fused: h2 finalize + SHARED pooling (block owns 2 graphs) + feature attention ----------------
__global__ void att_k(const float* __restrict__ b2, const float* __restrict__ fab2) {
    __shared__ __align__(16) __half2 W1s[64 * 32];
    __shared__ float poolS[128 * 65];          // 65-stride: conflict-free scalar STS/LDS
    __shared__ __half2 b1s[32], w2s[32];
    __shared__ float b2s[64];
    __shared__ float fas[64];
    int tid = threadIdx.x;  // 128
    for (int i = tid; i < 2048; i += 128) W1s[i] = d_faW1h[i];
    if (tid < 32) { b1s[tid] = d_fab1h[tid]; w2s[tid] = d_faW2h[tid]; }
    if (tid < 64) { b2s[tid] = b2[tid]; fas[tid] = 0.f; }
    __syncthreads();
    int n = blockIdx.x * 128 + tid;
    float inv = 1.f / d_den2[n];
    __half2 hh[32];
    float* prow = &poolS[tid * 65];
#pragma unroll
    for (int i = 0; i < 8; i++) {
        uint4 o4 = *(const uint4*)&d_out2h[n * 32 + i * 4];
        float2 f0 = __half22float2(*(__half2*)&o4.x);
        float2 f1 = __half22float2(*(__half2*)&o4.y);
        float2 f2 = __half22float2(*(__half2*)&o4.z);
        float2 f3 = __half22float2(*(__half2*)&o4.w);
        float h0 = fmaxf(f0.x * inv + b2s[i * 8 + 0], 0.f);
        float h1 = fmaxf(f0.y * inv + b2s[i * 8 + 1], 0.f);
        float h2 = fmaxf(f1.x * inv + b2s[i * 8 + 2], 0.f);
        float h3 = fmaxf(f1.y * inv + b2s[i * 8 + 3], 0.f);
        float h4 = fmaxf(f2.x * inv + b2s[i * 8 + 4], 0.f);
        float h5 = fmaxf(f2.y * inv + b2s[i * 8 + 5], 0.f);
        float h6 = fmaxf(f3.x * inv + b2s[i * 8 + 6], 0.f);
        float h7 = fmaxf(f3.y * inv + b2s[i * 8 + 7], 0.f);
        prow[i * 8 + 0] = h0; prow[i * 8 + 1] = h1;
        prow[i * 8 + 2] = h2; prow[i * 8 + 3] = h3;
        prow[i * 8 + 4] = h4; prow[i * 8 + 5] = h5;
        prow[i * 8 + 6] = h6; prow[i * 8 + 7] = h7;
        hh[i * 4 + 0] = __floats2half2_rn(h0, h1);
        hh[i * 4 + 1] = __floats2half2_rn(h2, h3);
        hh[i * 4 + 2] = __floats2half2_rn(h4, h5);
        hh[i * 4 + 3] = __floats2half2_rn(h6, h7);
    }
    __syncthreads();
    // pool: block owns graphs 2*blockIdx and 2*blockIdx+1; thread (g, c) sums 64 rows
    {
        int g = tid >> 6, c = tid & 63;
        const float* base = &poolS[g * 64 * 65 + c];
        float s = 0.f;
#pragma unroll 8
        for (int r = 0; r < 64; r++) s += base[r * 65];
        d_pool[(blockIdx.x * 2 + g) * 64 + c] = s;      // exclusive ownership: plain STG
    }
    __half2 acc[32];
#pragma unroll
    for (int i = 0; i < 32; i++) acc[i] = b1s[i];
#pragma unroll
    for (int ci = 0; ci < 32; ci++) {
        __half2 hc0 = __low2half2(hh[ci]);
        __half2 hc1 = __high2half2(hh[ci]);
        const uint4* wr0 = (const uint4*)&W1s[(2 * ci) * 32];
        const uint4* wr1 = (const uint4*)&W1s[(2 * ci + 1) * 32];
#pragma unroll
        for (int i = 0; i < 8; i++) {
            uint4 w0 = wr0[i];
            acc[i * 4 + 0] = __hfma2(hc0, *(__half2*)&w0.x, acc[i * 4 + 0]);
            acc[i * 4 + 1] = __hfma2(hc0, *(__half2*)&w0.y, acc[i * 4 + 1]);
            acc[i * 4 + 2] = __hfma2(hc0, *(__half2*)&w0.z, acc[i * 4 + 2]);
            acc[i * 4 + 3] = __hfma2(hc0, *(__half2*)&w0.w, acc[i * 4 + 3]);
        }
#pragma unroll
        for (int i = 0; i < 8; i++) {
            uint4 w1 = wr1[i];
            acc[i * 4 + 0] = __hfma2(hc1, *(__half2*)&w1.x, acc[i * 4 + 0]);
            acc[i * 4 + 1] = __hfma2(hc1, *(__half2*)&w1.y, acc[i * 4 + 1]);
            acc[i * 4 + 2] = __hfma2(hc1, *(__half2*)&w1.z, acc[i * 4 + 2]);
            acc[i * 4 + 3] = __hfma2(hc1, *(__half2*)&w1.w, acc[i * 4 + 3]);
        }
    }
    __half2 zero2 = __float2half2_rn(0.f);
    __half2 rs = zero2;
#pragma unroll
    for (int i = 0; i < 32; i++)
        rs = __hfma2(__hmax2(acc[i], zero2), w2s[i], rs);
    float res = fab2[0] + __low2float(rs) + __high2float(rs);
    float att = 1.f / (1.f + __expf(-res));
    atomicAdd(&fas[n & 63], att);
    __syncthreads();
    if (tid < 64) atomicAdd(&d_fa[tid], fas[tid]);
}

// ---------------- classifier + final_attention ----------------
__global__ void fin_k(const float* __restrict__ clsW, const float* __restrict__ clsb,
                      float* __restrict__ out) {
    if (blockIdx.x < 4) {
        int b = blockIdx.x * 256 + threadIdx.x;
        const float inv = 1.f / (float)FEATN;
        float p[64];
#pragma unroll
        for (int i = 0; i < 16; i++) {
            float4 v = *(const float4*)&d_pool[b * 64 + i * 4];
            p[i * 4] = v.x * inv; p[i * 4 + 1] = v.y * inv;
            p[i * 4 + 2] = v.z * inv; p[i * 4 + 3] = v.w * inv;
        }
#pragma unroll
        for (int j = 0; j < NCLS; j++) {
            float o = clsb[j];
#pragma unroll
            for (int c = 0; c < 64; c++) o += p[c] * clsW[c * NCLS + j];
            out[b * NCLS + j] = o;
        }
    } else {
        int f = threadIdx.x;
        if (f < 64) out[BB * NCLS + f] = d_fa[f] * (1.f / (float)BB);
    }
}

extern "C" void kernel_launch(void* const* d_in, const int* in_sizes, int n_in,
                              void* d_out, int out_size) {
    const float* x    = (const float*)d_in[0];
    const int*   ei   = (const int*)d_in[1];
    const float* Win  = (const float*)d_in[3];
    const float* bin  = (const float*)d_in[4];
    const float* W1   = (const float*)d_in[5];
    const float* a1s  = (const float*)d_in[6];
    const float* a1d  = (const float*)d_in[7];
    const float* b1   = (const float*)d_in[8];
    const float* W2   = (const float*)d_in[9];
    const float* a2s  = (const float*)d_in[10];
    const float* a2d  = (const float*)d_in[11];
    const float* b2   = (const float*)d_in[12];
    const float* faW1 = (const float*)d_in[13];
    const float* fab1 = (const float*)d_in[14];
    const float* faW2 = (const float*)d_in[15];
    const float* fab2 = (const float*)d_in[16];
    const float* clsW = (const float*)d_in[17];
    const float* clsb = (const float*)d_in[18];
    float* out = (float*)d_out;

    init_k<<<160, 256>>>(x, Win, bin, W1, a1s, a1d, b1, W2, a2s, a2d, faW1, fab1, faW2);
    gat1_k<<<EE / 256, 256>>>(ei, x);
    g2_k<<<NN / 8, 256>>>();
    gat2_k<<<EE / 512, 256>>>(ei);
    att_k<<<NN / 128, 128>>>(b2, fab2);
    fin_k<<<5, 256>>>(clsW, clsb, out);
}